// round 12
// baseline (speedup 1.0000x reference)
#include <cuda_runtime.h>
#include <math.h>
#include <stdint.h>

#define B_    1024
#define C_    1024
#define E_    128
#define SPLIT 4
#define RPB   (C_ / SPLIT)    // 256 rows per fused block
#define TROWS 64              // rows per pipeline stage (32KB)
#define NT    (RPB / TROWS)   // 4 stages

// ---------------- device scratch (allocation-free rule) ----------------
__device__ float g_u [B_ * 8 * E_];
__device__ float g_qb[B_ * 8];
__device__ float g_pl[B_ * SPLIT * 8];
__device__ float g_ps[(size_t)B_ * SPLIT * 8 * E_];
__device__ float g_w [B_ * E_];
__device__ float g_kb[B_];

// ---------------- f32x2 helpers ----------------
__device__ __forceinline__ unsigned long long pk2(float x, float y) {
    unsigned long long r;
    asm("mov.b64 %0, {%1, %2};" : "=l"(r) : "f"(x), "f"(y));
    return r;
}
__device__ __forceinline__ float2 upk2(unsigned long long v) {
    float2 r;
    asm("mov.b64 {%0, %1}, %2;" : "=f"(r.x), "=f"(r.y) : "l"(v));
    return r;
}
#define FMA2(d, a, b) asm("fma.rn.f32x2 %0, %1, %2, %0;" : "+l"(d) : "l"(a), "l"(b))

__device__ __forceinline__ void cp16(unsigned int dst, const void* src) {
    asm volatile("cp.async.cg.shared.global [%0], [%1], 16;" :: "r"(dst), "l"(src));
}

// ---------------------------------------------------------------------------
// K0: per batch — q = Qw@hc + Qb;  u[h][:] = 0.25 q_h^T Vw_h;  qb[h] = 0.25 q_h.Vb_h
// ---------------------------------------------------------------------------
__global__ void __launch_bounds__(128) k_prep(
    const float* __restrict__ hN, const float* __restrict__ hpr,
    const float* __restrict__ h0,
    const float* __restrict__ Qw, const float* __restrict__ Qb,
    const float* __restrict__ Vw, const float* __restrict__ Vb)
{
    const int b = blockIdx.x, tid = threadIdx.x;
    __shared__ float hc_s[384];
    __shared__ float q_s[128];

    hc_s[tid]       = hN [b * E_ + tid];
    hc_s[128 + tid] = hpr[b * E_ + tid];
    hc_s[256 + tid] = h0 [b * E_ + tid];
    __syncthreads();

    {
        float a = Qb[tid];
        const float4* qr = (const float4*)(Qw + (size_t)tid * 384);
        const float4* xc = (const float4*)hc_s;
        #pragma unroll 8
        for (int i = 0; i < 96; i++) {
            float4 w = qr[i], x = xc[i];
            a += w.x * x.x + w.y * x.y + w.z * x.z + w.w * x.w;
        }
        q_s[tid] = a;
    }
    __syncthreads();

    const int k = tid;
    #pragma unroll
    for (int hh = 0; hh < 8; hh++) {
        float acc = 0.0f;
        #pragma unroll
        for (int j = 0; j < 16; j++)
            acc += q_s[hh * 16 + j] * Vw[(size_t)(hh * 16 + j) * E_ + k];
        g_u[((size_t)b * 8 + hh) * E_ + k] = 0.25f * acc;
    }
    if (tid < 8) {
        float a = 0.0f;
        #pragma unroll
        for (int j = 0; j < 16; j++)
            a += q_s[tid * 16 + j] * Vb[tid * 16 + j];
        g_qb[b * 8 + tid] = 0.25f * a;
    }
}

// ---------------------------------------------------------------------------
// K1: cp.async pipeline; transposed dot phase (lane=row, no shuffles);
//     wsum phase (lane=e-slice). XOR-swizzled smem tiles for both patterns.
// ---------------------------------------------------------------------------
__global__ void __launch_bounds__(256, 2) k_fused(const float* __restrict__ h,
                                                  const int*   __restrict__ mask)
{
    const int b = blockIdx.y, part = blockIdx.x;
    const int tid = threadIdx.x, warp = tid >> 5, lane = tid & 31;

    extern __shared__ float hbuf[];        // 2 stages x 8192 floats (64KB), swizzled
    __shared__ float u_s[8 * 128];
    __shared__ float qb_s[8];
    __shared__ int   mask_s[2][TROWS];
    __shared__ float p_s[TROWS * 8];       // [row][head]
    __shared__ float sl[8][2];

    const float* hb = h + ((size_t)b * C_ + part * RPB) * E_;
    const int*   mb = mask + b * C_ + part * RPB;

    // stage loader: 2048 16B chunks, swizzled dst (chunk j of row r -> j^(r&31))
    auto load_stage = [&](int t) {
        float* dst = hbuf + (t & 1) * 8192;
        const float* src = hb + (size_t)t * TROWS * E_;
        #pragma unroll
        for (int k = 0; k < 8; k++) {
            int idx = k * 256 + tid;
            int r = idx >> 5, j = idx & 31;
            unsigned int d = (unsigned int)__cvta_generic_to_shared(
                dst + r * 128 + ((j ^ (r & 31)) << 2));
            cp16(d, src + (size_t)idx * 4);
        }
        if (tid < 16) {
            unsigned int dm = (unsigned int)__cvta_generic_to_shared(&mask_s[t & 1][tid * 4]);
            cp16(dm, mb + t * TROWS + tid * 4);
        }
    };

    load_stage(0);
    asm volatile("cp.async.commit_group;");
    load_stage(1);
    asm volatile("cp.async.commit_group;");

    // stage u, qb
    #pragma unroll
    for (int i = 0; i < 4; i++)
        u_s[tid + i * 256] = g_u[(size_t)b * 1024 + tid + i * 256];
    if (tid < 8) qb_s[tid] = g_qb[b * 8 + tid];

    // phase A role: rows half + head pair
    const int rA = (warp & 1) * 32 + lane;      // this lane's row within stage
    const int hp = (warp >> 1) * 2;             // head pair hp, hp+1

    unsigned long long s2[16];                  // all 8 heads x 2 packed pairs
    #pragma unroll
    for (int i = 0; i < 16; i++) s2[i] = pk2(0.f, 0.f);
    float l0 = 0.0f, l1 = 0.0f;

    __syncthreads();                            // u_s visible
    const float qb0 = qb_s[hp], qb1 = qb_s[hp + 1];

    #pragma unroll 1
    for (int t = 0; t < NT; t++) {
        if (t == NT - 1) asm volatile("cp.async.wait_group 0;");
        else             asm volatile("cp.async.wait_group 1;");
        __syncthreads();

        const float* hs = hbuf + (t & 1) * 8192;
        const int*   ms = mask_s[t & 1];

        // ---- Phase A: dots (lane = row), 2 heads, no cross-lane reduction ----
        {
            const float* hr = hs + rA * 128;
            unsigned long long d0 = pk2(0.f, 0.f), d1 = pk2(0.f, 0.f);
            #pragma unroll
            for (int j = 0; j < 32; j++) {
                float4 h4 = *(const float4*)(hr + ((j ^ lane) << 2));
                float4 ua = *(const float4*)(u_s + hp * 128 + j * 4);
                float4 ub = *(const float4*)(u_s + (hp + 1) * 128 + j * 4);
                unsigned long long hxy = pk2(h4.x, h4.y);
                unsigned long long hzw = pk2(h4.z, h4.w);
                FMA2(d0, hxy, pk2(ua.x, ua.y));
                FMA2(d0, hzw, pk2(ua.z, ua.w));
                FMA2(d1, hxy, pk2(ub.x, ub.y));
                FMA2(d1, hzw, pk2(ub.z, ub.w));
            }
            float2 t0 = upk2(d0), t1 = upk2(d1);
            float mv = (float)ms[rA] * 1.0e8f;
            float p0 = __expf(t0.x + t0.y + qb0 - mv);
            float p1 = __expf(t1.x + t1.y + qb1 - mv);
            l0 += p0; l1 += p1;
            p_s[rA * 8 + hp]     = p0;
            p_s[rA * 8 + hp + 1] = p1;
        }
        __syncthreads();

        // ---- Phase B: weighted sums (lane = e-slice), 8 rows per warp ----
        {
            #pragma unroll
            for (int rr = 0; rr < 8; rr++) {
                int r = warp * 8 + rr;
                float4 h4 = *(const float4*)(hs + r * 128 + ((lane ^ (r & 31)) << 2));
                float4 pa = *(const float4*)(p_s + r * 8);
                float4 pb = *(const float4*)(p_s + r * 8 + 4);
                unsigned long long hxy = pk2(h4.x, h4.y);
                unsigned long long hzw = pk2(h4.z, h4.w);
                unsigned long long pd;
                pd = pk2(pa.x, pa.x); FMA2(s2[0],  hxy, pd); FMA2(s2[1],  hzw, pd);
                pd = pk2(pa.y, pa.y); FMA2(s2[2],  hxy, pd); FMA2(s2[3],  hzw, pd);
                pd = pk2(pa.z, pa.z); FMA2(s2[4],  hxy, pd); FMA2(s2[5],  hzw, pd);
                pd = pk2(pa.w, pa.w); FMA2(s2[6],  hxy, pd); FMA2(s2[7],  hzw, pd);
                pd = pk2(pb.x, pb.x); FMA2(s2[8],  hxy, pd); FMA2(s2[9],  hzw, pd);
                pd = pk2(pb.y, pb.y); FMA2(s2[10], hxy, pd); FMA2(s2[11], hzw, pd);
                pd = pk2(pb.z, pb.z); FMA2(s2[12], hxy, pd); FMA2(s2[13], hzw, pd);
                pd = pk2(pb.w, pb.w); FMA2(s2[14], hxy, pd); FMA2(s2[15], hzw, pd);
            }
        }
        __syncthreads();

        if (t + 2 < NT) {
            load_stage(t + 2);
            asm volatile("cp.async.commit_group;");
        }
    }

    // ---- combine: reuse hbuf as [warp][head][e] = 32KB ----
    float* sm = hbuf;
    #pragma unroll
    for (int hh = 0; hh < 8; hh++) {
        float2 e01 = upk2(s2[2 * hh]);
        float2 e23 = upk2(s2[2 * hh + 1]);
        *(float4*)&sm[warp * 1024 + hh * 128 + lane * 4] =
            make_float4(e01.x, e01.y, e23.x, e23.y);
    }
    // l: reduce over lanes (rows)
    #pragma unroll
    for (int off = 16; off; off >>= 1) {
        l0 += __shfl_xor_sync(0xffffffffu, l0, off);
        l1 += __shfl_xor_sync(0xffffffffu, l1, off);
    }
    if (lane == 0) { sl[warp][0] = l0; sl[warp][1] = l1; }
    __syncthreads();

    const size_t base = (size_t)(b * SPLIT + part) * 8 * E_;
    #pragma unroll
    for (int k = 0; k < 4; k++) {
        int idx = tid + k * 256;
        float a = 0.0f;
        #pragma unroll
        for (int w = 0; w < 8; w++) a += sm[w * 1024 + idx];
        g_ps[base + idx] = a;
    }
    if (tid < 8) {
        int w0 = tid & ~1;                 // warps w0, w0+1 hold head pair (tid>>1)*2
        g_pl[(b * SPLIT + part) * 8 + tid] = sl[w0][tid & 1] + sl[w0 + 1][tid & 1];
    }
}

// ---------------------------------------------------------------------------
// K2: per batch — combine partials -> sbar -> ctx -> dec -> qf -> (w, kb)
// ---------------------------------------------------------------------------
__global__ void __launch_bounds__(128) k_epilogue(
    const float* __restrict__ Vw,  const float* __restrict__ Vb,
    const float* __restrict__ Wow, const float* __restrict__ Wob,
    const float* __restrict__ Qfw, const float* __restrict__ Qfb,
    const float* __restrict__ Kfw, const float* __restrict__ Kfb)
{
    const int b = blockIdx.x, tid = threadIdx.x;
    __shared__ float sbar[1024], ctx[128], dec[128], qf[128], r2[128];
    __shared__ float invl[8];

    if (tid < 8) {
        float L = 0.0f;
        #pragma unroll
        for (int p = 0; p < SPLIT; p++)
            L += g_pl[(b * SPLIT + p) * 8 + tid];
        invl[tid] = 1.0f / L;
    }
    __syncthreads();

    #pragma unroll
    for (int hh = 0; hh < 8; hh++) {
        float a = 0.0f;
        #pragma unroll
        for (int p = 0; p < SPLIT; p++)
            a += g_ps[(size_t)(b * SPLIT + p) * 8 * E_ + hh * E_ + tid];
        sbar[hh * 128 + tid] = a * invl[hh];
    }
    __syncthreads();

    {
        const int head = tid >> 4;
        float a = Vb[tid];
        const float4* wr = (const float4*)(Vw + (size_t)tid * E_);
        const float4* xc = (const float4*)&sbar[head * 128];
        #pragma unroll 8
        for (int i = 0; i < 32; i++) {
            float4 w = wr[i], x = xc[i];
            a += w.x * x.x + w.y * x.y + w.z * x.z + w.w * x.w;
        }
        ctx[tid] = a;
    }
    __syncthreads();
    {
        float a = Wob[tid];
        const float4* wr = (const float4*)(Wow + (size_t)tid * E_);
        const float4* xc = (const float4*)ctx;
        #pragma unroll 8
        for (int i = 0; i < 32; i++) {
            float4 w = wr[i], x = xc[i];
            a += w.x * x.x + w.y * x.y + w.z * x.z + w.w * x.w;
        }
        dec[tid] = a;
    }
    __syncthreads();
    {
        float a = Qfb[tid];
        const float4* wr = (const float4*)(Qfw + (size_t)tid * E_);
        const float4* xc = (const float4*)dec;
        #pragma unroll 8
        for (int i = 0; i < 32; i++) {
            float4 w = wr[i], x = xc[i];
            a += w.x * x.x + w.y * x.y + w.z * x.z + w.w * x.w;
        }
        qf[tid] = a;
    }
    __syncthreads();

    {
        float a = 0.0f;
        #pragma unroll 8
        for (int j = 0; j < 128; j++)
            a += qf[j] * Kfw[(size_t)j * E_ + tid];
        g_w[b * 128 + tid] = a;
    }
    r2[tid] = qf[tid] * Kfb[tid];
    __syncthreads();
    for (int st = 64; st; st >>= 1) {
        if (tid < st) r2[tid] += r2[tid + st];
        __syncthreads();
    }
    if (tid == 0) g_kb[b] = r2[0];
}

// ---------------------------------------------------------------------------
// K3: logits[b][c] = 10*tanh((h.w + kb)/sqrt(E)) - mask*1e8  (paired-row fold)
// ---------------------------------------------------------------------------
__global__ void __launch_bounds__(256) k_logits(
    const float* __restrict__ h, const int* __restrict__ mask,
    float* __restrict__ out)
{
    const int b = blockIdx.y, chunk = blockIdx.x;
    const int warp = threadIdx.x >> 5, lane = threadIdx.x & 31;

    float4 w4 = *(const float4*)&g_w[b * 128 + lane * 4];
    float  kb = g_kb[b];

    const int c0 = chunk * 256 + warp * 32;
    const float* rp = h + ((size_t)b * C_ + c0) * E_ + lane * 4;
    const bool hi = (lane & 16) != 0;
    const int  sub = lane >> 4;

    float4 a0 = *(const float4*)rp;
    float4 a1 = *(const float4*)(rp + E_);

    #pragma unroll 2
    for (int j = 0; j < 16; j++) {
        float4 r0 = a0, r1 = a1;
        if (j < 15) {
            a0 = *(const float4*)(rp + (size_t)(2 * j + 2) * E_);
            a1 = *(const float4*)(rp + (size_t)(2 * j + 3) * E_);
        }
        float p0 = r0.x * w4.x + r0.y * w4.y + r0.z * w4.z + r0.w * w4.w;
        float p1 = r1.x * w4.x + r1.y * w4.y + r1.z * w4.z + r1.w * w4.w;

        float send = hi ? p0 : p1;
        float keep = hi ? p1 : p0;
        float t = keep + __shfl_xor_sync(0xffffffffu, send, 16);
        t += __shfl_xor_sync(0xffffffffu, t, 8);
        t += __shfl_xor_sync(0xffffffffu, t, 4);
        t += __shfl_xor_sync(0xffffffffu, t, 2);
        t += __shfl_xor_sync(0xffffffffu, t, 1);

        if ((lane & 15) == 0) {
            int c = c0 + 2 * j + sub;
            float lg = (t + kb) * 0.08838834764831845f;
            out[(size_t)b * C_ + c] =
                10.0f * tanhf(lg) - (float)mask[b * C_ + c] * 1.0e8f;
        }
    }
}

// ---------------------------------------------------------------------------
extern "C" void kernel_launch(void* const* d_in, const int* in_sizes, int n_in,
                              void* d_out, int out_size) {
    const float* h    = (const float*)d_in[0];
    const float* hN   = (const float*)d_in[1];
    const float* hpr  = (const float*)d_in[2];
    const float* h0   = (const float*)d_in[3];
    const int*   mask = (const int*)  d_in[4];
    const float* Qw   = (const float*)d_in[5];
    const float* Qb   = (const float*)d_in[6];
    const float* Vw   = (const float*)d_in[7];
    const float* Vb   = (const float*)d_in[8];
    const float* Wow  = (const float*)d_in[9];
    const float* Wob  = (const float*)d_in[10];
    const float* Qfw  = (const float*)d_in[11];
    const float* Qfb  = (const float*)d_in[12];
    const float* Kfw  = (const float*)d_in[13];
    const float* Kfb  = (const float*)d_in[14];
    float* out = (float*)d_out;

    const int DSMEM = 2 * TROWS * E_ * (int)sizeof(float);   // 64 KB
    cudaFuncSetAttribute(k_fused, cudaFuncAttributeMaxDynamicSharedMemorySize, DSMEM);

    k_prep    <<<B_, 128>>>(hN, hpr, h0, Qw, Qb, Vw, Vb);
    k_fused   <<<dim3(SPLIT, B_), 256, DSMEM>>>(h, mask);
    k_epilogue<<<B_, 128>>>(Vw, Vb, Wow, Wob, Qfw, Qfb, Kfw, Kfb);
    k_logits  <<<dim3(4, B_), 256>>>(h, mask, out);
}

// round 13
// speedup vs baseline: 1.2726x; 1.2726x over previous
#include <cuda_runtime.h>
#include <math.h>
#include <stdint.h>

#define B_    1024
#define C_    1024
#define E_    128
#define SPLIT 4
#define RPB   (C_ / SPLIT)    // 256 rows per fused block
#define TROWS 64              // rows per pipeline stage (32KB)
#define NT    (RPB / TROWS)   // 4 stages

// ---------------- device scratch (allocation-free rule) ----------------
__device__ float g_u [B_ * 8 * E_];
__device__ float g_qb[B_ * 8];
__device__ float g_pl[B_ * SPLIT * 8];
__device__ float g_ps[(size_t)B_ * SPLIT * 8 * E_];
__device__ float g_w [B_ * E_];
__device__ float g_kb[B_];

// ---------------- f32x2 helpers ----------------
__device__ __forceinline__ unsigned long long pk2(float x, float y) {
    unsigned long long r;
    asm("mov.b64 %0, {%1, %2};" : "=l"(r) : "f"(x), "f"(y));
    return r;
}
__device__ __forceinline__ float2 upk2(unsigned long long v) {
    float2 r;
    asm("mov.b64 {%0, %1}, %2;" : "=f"(r.x), "=f"(r.y) : "l"(v));
    return r;
}
#define MUL2(d, a, b) asm("mul.rn.f32x2 %0, %1, %2;" : "=l"(d) : "l"(a), "l"(b))
#define FMA2(d, a, b) asm("fma.rn.f32x2 %0, %1, %2, %0;" : "+l"(d) : "l"(a), "l"(b))

__device__ __forceinline__ void cp16(unsigned int dst, const void* src) {
    asm volatile("cp.async.cg.shared.global [%0], [%1], 16;" :: "r"(dst), "l"(src));
}

// ---------------------------------------------------------------------------
// K0: per batch — q = Qw@hc + Qb;  u[h][:] = 0.25 q_h^T Vw_h;  qb[h] = 0.25 q_h.Vb_h
// ---------------------------------------------------------------------------
__global__ void __launch_bounds__(128) k_prep(
    const float* __restrict__ hN, const float* __restrict__ hpr,
    const float* __restrict__ h0,
    const float* __restrict__ Qw, const float* __restrict__ Qb,
    const float* __restrict__ Vw, const float* __restrict__ Vb)
{
    const int b = blockIdx.x, tid = threadIdx.x;
    __shared__ float hc_s[384];
    __shared__ float q_s[128];

    hc_s[tid]       = hN [b * E_ + tid];
    hc_s[128 + tid] = hpr[b * E_ + tid];
    hc_s[256 + tid] = h0 [b * E_ + tid];
    __syncthreads();

    {
        float a = Qb[tid];
        const float4* qr = (const float4*)(Qw + (size_t)tid * 384);
        const float4* xc = (const float4*)hc_s;
        #pragma unroll 8
        for (int i = 0; i < 96; i++) {
            float4 w = qr[i], x = xc[i];
            a += w.x * x.x + w.y * x.y + w.z * x.z + w.w * x.w;
        }
        q_s[tid] = a;
    }
    __syncthreads();

    const int k = tid;
    #pragma unroll
    for (int hh = 0; hh < 8; hh++) {
        float acc = 0.0f;
        #pragma unroll
        for (int j = 0; j < 16; j++)
            acc += q_s[hh * 16 + j] * Vw[(size_t)(hh * 16 + j) * E_ + k];
        g_u[((size_t)b * 8 + hh) * E_ + k] = 0.25f * acc;
    }
    if (tid < 8) {
        float a = 0.0f;
        #pragma unroll
        for (int j = 0; j < 16; j++)
            a += q_s[tid * 16 + j] * Vb[tid * 16 + j];
        g_qb[b * 8 + tid] = 0.25f * a;
    }
}

// ---------------------------------------------------------------------------
// K1: cp.async double-buffered tiles; warp-pair heads; ballot-driven skip of
//     masked rows (their softmax weight is exactly 0).
// ---------------------------------------------------------------------------
__global__ void __launch_bounds__(256, 2) k_fused(const float* __restrict__ h,
                                                  const int*   __restrict__ mask)
{
    const int b = blockIdx.y, part = blockIdx.x;
    const int tid = threadIdx.x, warp = tid >> 5, lane = tid & 31;
    const int hg = warp >> 2;       // head group: heads hg*4 .. hg*4+3
    const int ws = warp & 3;        // row stream within tile

    extern __shared__ float hbuf[];            // 2 stages x 8192 floats (64KB)
    __shared__ int   mask_s[2][TROWS];
    __shared__ float p_s[8][2][4];

    const float* hb = h + ((size_t)b * C_ + part * RPB) * E_;
    const int*   mb = mask + b * C_ + part * RPB;

    auto load_stage = [&](int t) {
        float* dst = hbuf + (t & 1) * 8192;
        const float* src = hb + (size_t)t * TROWS * E_;
        unsigned int d0 = (unsigned int)__cvta_generic_to_shared(dst + tid * 4);
        #pragma unroll
        for (int k = 0; k < 8; k++)
            cp16(d0 + k * 4096, src + k * 1024 + tid * 4);
        if (tid < 16) {
            unsigned int dm = (unsigned int)__cvta_generic_to_shared(&mask_s[t & 1][tid * 4]);
            cp16(dm, mb + t * TROWS + tid * 4);
        }
    };

    load_stage(0);
    asm volatile("cp.async.commit_group;");
    load_stage(1);
    asm volatile("cp.async.commit_group;");

    // u for this warp's 4 heads
    unsigned long long u01[4], u23[4];
    #pragma unroll
    for (int hh = 0; hh < 4; hh++) {
        float4 uu = *(const float4*)&g_u[((size_t)b * 8 + hg * 4 + hh) * E_ + lane * 4];
        u01[hh] = pk2(uu.x, uu.y);
        u23[hh] = pk2(uu.z, uu.w);
    }
    const float qbr = g_qb[b * 8 + hg * 4 + (lane >> 3)];

    unsigned long long s2[8];
    #pragma unroll
    for (int i = 0; i < 8; i++) s2[i] = pk2(0.f, 0.f);
    float l_acc = 0.0f;

    const bool hi4 = (lane & 16) != 0;
    const bool hi3 = (lane & 8)  != 0;

    #pragma unroll 1
    for (int t = 0; t < NT; t++) {
        if (t == NT - 1) asm volatile("cp.async.wait_group 0;");
        else             asm volatile("cp.async.wait_group 1;");
        __syncthreads();

        const float* hs = hbuf + (t & 1) * 8192;
        const int*   ms = mask_s[t & 1];

        // unmasked-row bitmask for this stream (rows ws + 4i, i in [0,16))
        int mrow = (lane < 16) ? ms[ws + 4 * lane] : 1;
        unsigned bits = __ballot_sync(0xffffffffu, mrow == 0) & 0xffffu;

        while (bits) {
            int i0 = __ffs(bits) - 1; bits &= bits - 1;
            int i1 = i0; float v1 = 0.0f;
            if (bits) { i1 = __ffs(bits) - 1; bits &= bits - 1; v1 = 1.0f; }
            const int r0 = ws + 4 * i0, r1 = ws + 4 * i1;

            float4 c0 = *(const float4*)&hs[r0 * 128 + lane * 4];
            float4 c1 = *(const float4*)&hs[r1 * 128 + lane * 4];
            unsigned long long cxy0 = pk2(c0.x, c0.y), czw0 = pk2(c0.z, c0.w);
            unsigned long long cxy1 = pk2(c1.x, c1.y), czw1 = pk2(c1.z, c1.w);

            // dots: 2 rows x 4 heads
            float d[2][4];
            #pragma unroll
            for (int hh = 0; hh < 4; hh++) {
                unsigned long long t0, t1;
                MUL2(t0, cxy0, u01[hh]); FMA2(t0, czw0, u23[hh]);
                MUL2(t1, cxy1, u01[hh]); FMA2(t1, czw1, u23[hh]);
                float2 a0 = upk2(t0), a1 = upk2(t1);
                d[0][hh] = a0.x + a0.y;
                d[1][hh] = a1.x + a1.y;
            }

            // head folding -> lane>>3 head, level-major across 2 rows
            #pragma unroll
            for (int j = 0; j < 2; j++)
                #pragma unroll
                for (int q = 0; q < 2; q++) {
                    float send = hi4 ? d[j][q] : d[j][q + 2];
                    float keep = hi4 ? d[j][q + 2] : d[j][q];
                    d[j][q] = keep + __shfl_xor_sync(0xffffffffu, send, 16);
                }
            float dd[2];
            #pragma unroll
            for (int j = 0; j < 2; j++) {
                float send = hi3 ? d[j][0] : d[j][1];
                float keep = hi3 ? d[j][1] : d[j][0];
                dd[j] = keep + __shfl_xor_sync(0xffffffffu, send, 8);
            }
            #pragma unroll
            for (int j = 0; j < 2; j++)
                dd[j] += __shfl_xor_sync(0xffffffffu, dd[j], 4);
            #pragma unroll
            for (int j = 0; j < 2; j++)
                dd[j] += __shfl_xor_sync(0xffffffffu, dd[j], 2);
            #pragma unroll
            for (int j = 0; j < 2; j++)
                dd[j] += __shfl_xor_sync(0xffffffffu, dd[j], 1);

            float p0 = __expf(dd[0] + qbr);
            float p1 = __expf(dd[1] + qbr) * v1;   // dup row contributes 0
            l_acc += p0 + p1;

            __syncwarp();
            if ((lane & 7) == 0) {
                p_s[warp][0][lane >> 3] = p0;
                p_s[warp][1][lane >> 3] = p1;
            }
            __syncwarp();

            float4 pq0 = *(const float4*)&p_s[warp][0][0];
            float4 pq1 = *(const float4*)&p_s[warp][1][0];
            unsigned long long pd;
            pd = pk2(pq0.x, pq0.x); FMA2(s2[0], cxy0, pd); FMA2(s2[1], czw0, pd);
            pd = pk2(pq0.y, pq0.y); FMA2(s2[2], cxy0, pd); FMA2(s2[3], czw0, pd);
            pd = pk2(pq0.z, pq0.z); FMA2(s2[4], cxy0, pd); FMA2(s2[5], czw0, pd);
            pd = pk2(pq0.w, pq0.w); FMA2(s2[6], cxy0, pd); FMA2(s2[7], czw0, pd);
            pd = pk2(pq1.x, pq1.x); FMA2(s2[0], cxy1, pd); FMA2(s2[1], czw1, pd);
            pd = pk2(pq1.y, pq1.y); FMA2(s2[2], cxy1, pd); FMA2(s2[3], czw1, pd);
            pd = pk2(pq1.z, pq1.z); FMA2(s2[4], cxy1, pd); FMA2(s2[5], czw1, pd);
            pd = pk2(pq1.w, pq1.w); FMA2(s2[6], cxy1, pd); FMA2(s2[7], czw1, pd);
        }

        __syncthreads();
        if (t + 2 < NT) {
            load_stage(t + 2);
            asm volatile("cp.async.commit_group;");
        }
    }

    // combine: heads h<4 from warps 0-3, h>=4 from warps 4-7
    __shared__ float sm[8 * 4 * 128];    // 16 KB
    __shared__ float sl[8][4];
    #pragma unroll
    for (int hh = 0; hh < 4; hh++) {
        float2 e01 = upk2(s2[2 * hh]);
        float2 e23 = upk2(s2[2 * hh + 1]);
        *(float4*)&sm[warp * 512 + hh * 128 + lane * 4] =
            make_float4(e01.x, e01.y, e23.x, e23.y);
    }
    if ((lane & 7) == 0) sl[warp][lane >> 3] = l_acc;
    __syncthreads();

    const size_t base = (size_t)(b * SPLIT + part) * 8 * E_;
    #pragma unroll
    for (int k = 0; k < 4; k++) {
        int idx = tid + k * 256;
        int hh = idx >> 7, e = idx & 127;
        int w0 = (hh >> 2) * 4, hi = hh & 3;
        float a = 0.0f;
        #pragma unroll
        for (int w = 0; w < 4; w++) a += sm[(w0 + w) * 512 + hi * 128 + e];
        g_ps[base + idx] = a;
    }
    if (tid < 8) {
        int w0 = (tid >> 2) * 4, hi = tid & 3;
        float a = 0.0f;
        #pragma unroll
        for (int w = 0; w < 4; w++) a += sl[w0 + w][hi];
        g_pl[(b * SPLIT + part) * 8 + tid] = a;
    }
}

// ---------------------------------------------------------------------------
// K2: per batch — combine partials -> sbar -> ctx -> dec -> qf -> (w, kb)
// ---------------------------------------------------------------------------
__global__ void __launch_bounds__(128) k_epilogue(
    const float* __restrict__ Vw,  const float* __restrict__ Vb,
    const float* __restrict__ Wow, const float* __restrict__ Wob,
    const float* __restrict__ Qfw, const float* __restrict__ Qfb,
    const float* __restrict__ Kfw, const float* __restrict__ Kfb)
{
    const int b = blockIdx.x, tid = threadIdx.x;
    __shared__ float sbar[1024], ctx[128], dec[128], qf[128], r2[128];
    __shared__ float invl[8];

    if (tid < 8) {
        float L = 0.0f;
        #pragma unroll
        for (int p = 0; p < SPLIT; p++)
            L += g_pl[(b * SPLIT + p) * 8 + tid];
        invl[tid] = 1.0f / L;
    }
    __syncthreads();

    #pragma unroll
    for (int hh = 0; hh < 8; hh++) {
        float a = 0.0f;
        #pragma unroll
        for (int p = 0; p < SPLIT; p++)
            a += g_ps[(size_t)(b * SPLIT + p) * 8 * E_ + hh * E_ + tid];
        sbar[hh * 128 + tid] = a * invl[hh];
    }
    __syncthreads();

    {
        const int head = tid >> 4;
        float a = Vb[tid];
        const float4* wr = (const float4*)(Vw + (size_t)tid * E_);
        const float4* xc = (const float4*)&sbar[head * 128];
        #pragma unroll 8
        for (int i = 0; i < 32; i++) {
            float4 w = wr[i], x = xc[i];
            a += w.x * x.x + w.y * x.y + w.z * x.z + w.w * x.w;
        }
        ctx[tid] = a;
    }
    __syncthreads();
    {
        float a = Wob[tid];
        const float4* wr = (const float4*)(Wow + (size_t)tid * E_);
        const float4* xc = (const float4*)ctx;
        #pragma unroll 8
        for (int i = 0; i < 32; i++) {
            float4 w = wr[i], x = xc[i];
            a += w.x * x.x + w.y * x.y + w.z * x.z + w.w * x.w;
        }
        dec[tid] = a;
    }
    __syncthreads();
    {
        float a = Qfb[tid];
        const float4* wr = (const float4*)(Qfw + (size_t)tid * E_);
        const float4* xc = (const float4*)dec;
        #pragma unroll 8
        for (int i = 0; i < 32; i++) {
            float4 w = wr[i], x = xc[i];
            a += w.x * x.x + w.y * x.y + w.z * x.z + w.w * x.w;
        }
        qf[tid] = a;
    }
    __syncthreads();

    {
        float a = 0.0f;
        #pragma unroll 8
        for (int j = 0; j < 128; j++)
            a += qf[j] * Kfw[(size_t)j * E_ + tid];
        g_w[b * 128 + tid] = a;
    }
    r2[tid] = qf[tid] * Kfb[tid];
    __syncthreads();
    for (int st = 64; st; st >>= 1) {
        if (tid < st) r2[tid] += r2[tid + st];
        __syncthreads();
    }
    if (tid == 0) g_kb[b] = r2[0];
}

// ---------------------------------------------------------------------------
// K3: logits. Masked rows: write -1e8 and never touch h (tanh term <= 10 vs
//     1e8 -> norm rel_err ~5e-8). Unmasked rows: paired fold with prefetch.
// ---------------------------------------------------------------------------
__global__ void __launch_bounds__(256) k_logits(
    const float* __restrict__ h, const int* __restrict__ mask,
    float* __restrict__ out)
{
    const int b = blockIdx.y, chunk = blockIdx.x;
    const int warp = threadIdx.x >> 5, lane = threadIdx.x & 31;

    float4 w4 = *(const float4*)&g_w[b * 128 + lane * 4];
    float  kb = g_kb[b];

    const int c0 = chunk * 256 + warp * 32;
    const float* rbase = h + ((size_t)b * C_ + c0) * E_ + lane * 4;
    float* ob = out + (size_t)b * C_ + c0;

    const int m = mask[b * C_ + c0 + lane];
    unsigned bits = __ballot_sync(0xffffffffu, m == 0);
    if (m) ob[lane] = -1.0e8f;

    const bool hi = (lane & 16) != 0;

    int i0 = -1, i1 = -1;
    if (bits) { i0 = __ffs(bits) - 1; bits &= bits - 1; }
    if (bits) { i1 = __ffs(bits) - 1; bits &= bits - 1; }
    float4 A0 = make_float4(0.f, 0.f, 0.f, 0.f), A1 = A0;
    if (i0 >= 0) {
        A0 = *(const float4*)(rbase + (size_t)i0 * E_);
        A1 = *(const float4*)(rbase + (size_t)(i1 >= 0 ? i1 : i0) * E_);
    }

    while (i0 >= 0) {
        int n0 = -1, n1 = -1;
        if (bits) { n0 = __ffs(bits) - 1; bits &= bits - 1; }
        if (bits) { n1 = __ffs(bits) - 1; bits &= bits - 1; }
        float4 N0, N1;
        if (n0 >= 0) {
            N0 = *(const float4*)(rbase + (size_t)n0 * E_);
            N1 = *(const float4*)(rbase + (size_t)(n1 >= 0 ? n1 : n0) * E_);
        }

        float p0 = A0.x * w4.x + A0.y * w4.y + A0.z * w4.z + A0.w * w4.w;
        float p1 = A1.x * w4.x + A1.y * w4.y + A1.z * w4.z + A1.w * w4.w;

        float send = hi ? p0 : p1;
        float keep = hi ? p1 : p0;
        float t = keep + __shfl_xor_sync(0xffffffffu, send, 16);
        t += __shfl_xor_sync(0xffffffffu, t, 8);
        t += __shfl_xor_sync(0xffffffffu, t, 4);
        t += __shfl_xor_sync(0xffffffffu, t, 2);
        t += __shfl_xor_sync(0xffffffffu, t, 1);
        // lane 0: row i0 sum;  lane 16: row i1 sum

        float lg = (t + kb) * 0.08838834764831845f;   // 1/sqrt(128)
        float val = 10.0f * tanhf(lg);
        if (lane == 0)                 ob[i0] = val;
        else if (lane == 16 && i1 >= 0) ob[i1] = val;

        i0 = n0; i1 = n1; A0 = N0; A1 = N1;
    }
}

// ---------------------------------------------------------------------------
extern "C" void kernel_launch(void* const* d_in, const int* in_sizes, int n_in,
                              void* d_out, int out_size) {
    const float* h    = (const float*)d_in[0];
    const float* hN   = (const float*)d_in[1];
    const float* hpr  = (const float*)d_in[2];
    const float* h0   = (const float*)d_in[3];
    const int*   mask = (const int*)  d_in[4];
    const float* Qw   = (const float*)d_in[5];
    const float* Qb   = (const float*)d_in[6];
    const float* Vw   = (const float*)d_in[7];
    const float* Vb   = (const float*)d_in[8];
    const float* Wow  = (const float*)d_in[9];
    const float* Wob  = (const float*)d_in[10];
    const float* Qfw  = (const float*)d_in[11];
    const float* Qfb  = (const float*)d_in[12];
    const float* Kfw  = (const float*)d_in[13];
    const float* Kfb  = (const float*)d_in[14];
    float* out = (float*)d_out;

    const int DSMEM = 2 * TROWS * E_ * (int)sizeof(float);   // 64 KB
    cudaFuncSetAttribute(k_fused, cudaFuncAttributeMaxDynamicSharedMemorySize, DSMEM);

    k_prep    <<<B_, 128>>>(hN, hpr, h0, Qw, Qb, Vw, Vb);
    k_fused   <<<dim3(SPLIT, B_), 256, DSMEM>>>(h, mask);
    k_epilogue<<<B_, 128>>>(Vw, Vb, Wow, Wob, Qfw, Qfb, Kfw, Kfb);
    k_logits  <<<dim3(4, B_), 256>>>(h, mask, out);
}

// round 14
// speedup vs baseline: 1.3370x; 1.0506x over previous
#include <cuda_runtime.h>
#include <math.h>
#include <stdint.h>

#define B_    1024
#define C_    1024
#define E_    128
#define SPLIT 4
#define RPB   (C_ / SPLIT)    // 256 rows per fused block
#define TROWS 64              // compacted rows per pipeline stage (32KB)

// ---------------- device scratch (allocation-free rule) ----------------
__device__ float g_u [B_ * 8 * E_];
__device__ float g_qb[B_ * 8];
__device__ float g_pl[B_ * SPLIT * 8];
__device__ float g_ps[(size_t)B_ * SPLIT * 8 * E_];
__device__ float g_w [B_ * E_];
__device__ float g_kb[B_];
__device__ int   g_cidx[B_ * SPLIT * RPB];   // compacted unmasked row indices
__device__ int   g_cnt [B_ * SPLIT];         // counts

// ---------------- f32x2 helpers ----------------
__device__ __forceinline__ unsigned long long pk2(float x, float y) {
    unsigned long long r;
    asm("mov.b64 %0, {%1, %2};" : "=l"(r) : "f"(x), "f"(y));
    return r;
}
__device__ __forceinline__ float2 upk2(unsigned long long v) {
    float2 r;
    asm("mov.b64 {%0, %1}, %2;" : "=f"(r.x), "=f"(r.y) : "l"(v));
    return r;
}
#define MUL2(d, a, b) asm("mul.rn.f32x2 %0, %1, %2;" : "=l"(d) : "l"(a), "l"(b))
#define FMA2(d, a, b) asm("fma.rn.f32x2 %0, %1, %2, %0;" : "+l"(d) : "l"(a), "l"(b))

__device__ __forceinline__ void cp16(unsigned int dst, const void* src) {
    asm volatile("cp.async.cg.shared.global [%0], [%1], 16;" :: "r"(dst), "l"(src));
}

// ---------------------------------------------------------------------------
// K-compact: per (b, part): list of unmasked rows + count.
// ---------------------------------------------------------------------------
__global__ void __launch_bounds__(256) k_compact(const int* __restrict__ mask)
{
    const int bp = blockIdx.y * SPLIT + blockIdx.x;
    const int tid = threadIdx.x, warp = tid >> 5, lane = tid & 31;

    __shared__ int wcnt[8], woff[8];

    int m = mask[blockIdx.y * C_ + blockIdx.x * RPB + tid];
    unsigned bal = __ballot_sync(0xffffffffu, m == 0);
    int pin = __popc(bal & ((1u << lane) - 1));
    if (lane == 0) wcnt[warp] = __popc(bal);
    __syncthreads();
    if (tid < 8) {
        int o = 0;
        for (int w = 0; w < tid; w++) o += wcnt[w];
        woff[tid] = o;
    }
    __syncthreads();
    if (m == 0) g_cidx[bp * RPB + woff[warp] + pin] = tid;
    if (tid == 255) g_cnt[bp] = woff[7] + wcnt[7];
}

// ---------------------------------------------------------------------------
// K0: per batch — q = Qw@hc + Qb;  u[h][:] = 0.25 q_h^T Vw_h;  qb[h] = 0.25 q_h.Vb_h
// ---------------------------------------------------------------------------
__global__ void __launch_bounds__(128) k_prep(
    const float* __restrict__ hN, const float* __restrict__ hpr,
    const float* __restrict__ h0,
    const float* __restrict__ Qw, const float* __restrict__ Qb,
    const float* __restrict__ Vw, const float* __restrict__ Vb)
{
    const int b = blockIdx.x, tid = threadIdx.x;
    __shared__ float hc_s[384];
    __shared__ float q_s[128];

    hc_s[tid]       = hN [b * E_ + tid];
    hc_s[128 + tid] = hpr[b * E_ + tid];
    hc_s[256 + tid] = h0 [b * E_ + tid];
    __syncthreads();

    {
        float a = Qb[tid];
        const float4* qr = (const float4*)(Qw + (size_t)tid * 384);
        const float4* xc = (const float4*)hc_s;
        #pragma unroll 8
        for (int i = 0; i < 96; i++) {
            float4 w = qr[i], x = xc[i];
            a += w.x * x.x + w.y * x.y + w.z * x.z + w.w * x.w;
        }
        q_s[tid] = a;
    }
    __syncthreads();

    const int k = tid;
    #pragma unroll
    for (int hh = 0; hh < 8; hh++) {
        float acc = 0.0f;
        #pragma unroll
        for (int j = 0; j < 16; j++)
            acc += q_s[hh * 16 + j] * Vw[(size_t)(hh * 16 + j) * E_ + k];
        g_u[((size_t)b * 8 + hh) * E_ + k] = 0.25f * acc;
    }
    if (tid < 8) {
        float a = 0.0f;
        #pragma unroll
        for (int j = 0; j < 16; j++)
            a += q_s[tid * 16 + j] * Vb[tid * 16 + j];
        g_qb[b * 8 + tid] = 0.25f * a;
    }
}

// ---------------------------------------------------------------------------
// K1: compacted cp.async pipeline — only unmasked rows are ever loaded.
//     Warp pairs: warp w & w+4 process the same rows; each handles 4 heads.
// ---------------------------------------------------------------------------
__global__ void __launch_bounds__(256, 2) k_fused(const float* __restrict__ h)
{
    const int b = blockIdx.y, part = blockIdx.x;
    const int bp = b * SPLIT + part;
    const int tid = threadIdx.x, warp = tid >> 5, lane = tid & 31;
    const int hg = warp >> 2;       // head group: heads hg*4 .. hg*4+3
    const int ws = warp & 3;        // row stream within stage

    extern __shared__ float hbuf[];            // 2 stages x 8192 floats (64KB)
    __shared__ int   cidx_s[RPB];
    __shared__ float p_s[8][2][4];

    const float* hb = h + (size_t)b * C_ * E_ + (size_t)part * RPB * E_;

    const int nU = g_cnt[bp];
    const int ns = (nU + TROWS - 1) / TROWS;
    cidx_s[tid] = g_cidx[bp * RPB + tid];
    __syncthreads();

    auto load_stage = [&](int t) {
        float* dst = hbuf + (t & 1) * 8192;
        #pragma unroll
        for (int k = 0; k < 8; k++) {
            int idx = k * 256 + tid;           // 0..2047
            int i = t * TROWS + (idx >> 5);    // compact row index
            int j = idx & 31;                  // 16B chunk
            if (i < nU) {
                unsigned int d = (unsigned int)__cvta_generic_to_shared(
                    dst + (idx >> 5) * 128 + j * 4);
                cp16(d, hb + (size_t)cidx_s[i] * E_ + j * 4);
            }
        }
    };

    load_stage(0);
    asm volatile("cp.async.commit_group;");
    load_stage(1);
    asm volatile("cp.async.commit_group;");

    // u for this warp's 4 heads
    unsigned long long u01[4], u23[4];
    #pragma unroll
    for (int hh = 0; hh < 4; hh++) {
        float4 uu = *(const float4*)&g_u[((size_t)b * 8 + hg * 4 + hh) * E_ + lane * 4];
        u01[hh] = pk2(uu.x, uu.y);
        u23[hh] = pk2(uu.z, uu.w);
    }
    const float qbr = g_qb[b * 8 + hg * 4 + (lane >> 3)];

    unsigned long long s2[8];
    #pragma unroll
    for (int i = 0; i < 8; i++) s2[i] = pk2(0.f, 0.f);
    float l_acc = 0.0f;

    const bool hi4 = (lane & 16) != 0;
    const bool hi3 = (lane & 8)  != 0;

    #pragma unroll 1
    for (int t = 0; t < ns; t++) {
        if (t == ns - 1) asm volatile("cp.async.wait_group 0;");
        else             asm volatile("cp.async.wait_group 1;");
        __syncthreads();

        const float* hs = hbuf + (t & 1) * 8192;
        int cnt_s = nU - t * TROWS;
        if (cnt_s > TROWS) cnt_s = TROWS;

        #pragma unroll 1
        for (int i = 0; ws + 8 * i < cnt_s; i++) {
            const int r0 = ws + 8 * i;
            int r1 = r0 + 4; float v1 = 1.0f;
            if (r1 >= cnt_s) { r1 = r0; v1 = 0.0f; }

            float4 c0 = *(const float4*)&hs[r0 * 128 + lane * 4];
            float4 c1 = *(const float4*)&hs[r1 * 128 + lane * 4];
            unsigned long long cxy0 = pk2(c0.x, c0.y), czw0 = pk2(c0.z, c0.w);
            unsigned long long cxy1 = pk2(c1.x, c1.y), czw1 = pk2(c1.z, c1.w);

            // dots: 2 rows x 4 heads
            float d[2][4];
            #pragma unroll
            for (int hh = 0; hh < 4; hh++) {
                unsigned long long t0, t1;
                MUL2(t0, cxy0, u01[hh]); FMA2(t0, czw0, u23[hh]);
                MUL2(t1, cxy1, u01[hh]); FMA2(t1, czw1, u23[hh]);
                float2 a0 = upk2(t0), a1 = upk2(t1);
                d[0][hh] = a0.x + a0.y;
                d[1][hh] = a1.x + a1.y;
            }

            // head folding -> lane>>3 head, level-major across 2 rows
            #pragma unroll
            for (int j = 0; j < 2; j++)
                #pragma unroll
                for (int q = 0; q < 2; q++) {
                    float send = hi4 ? d[j][q] : d[j][q + 2];
                    float keep = hi4 ? d[j][q + 2] : d[j][q];
                    d[j][q] = keep + __shfl_xor_sync(0xffffffffu, send, 16);
                }
            float dd[2];
            #pragma unroll
            for (int j = 0; j < 2; j++) {
                float send = hi3 ? d[j][0] : d[j][1];
                float keep = hi3 ? d[j][1] : d[j][0];
                dd[j] = keep + __shfl_xor_sync(0xffffffffu, send, 8);
            }
            #pragma unroll
            for (int j = 0; j < 2; j++)
                dd[j] += __shfl_xor_sync(0xffffffffu, dd[j], 4);
            #pragma unroll
            for (int j = 0; j < 2; j++)
                dd[j] += __shfl_xor_sync(0xffffffffu, dd[j], 2);
            #pragma unroll
            for (int j = 0; j < 2; j++)
                dd[j] += __shfl_xor_sync(0xffffffffu, dd[j], 1);

            float p0 = __expf(dd[0] + qbr);
            float p1 = __expf(dd[1] + qbr) * v1;   // dup row contributes 0
            l_acc += p0 + p1;

            __syncwarp();
            if ((lane & 7) == 0) {
                p_s[warp][0][lane >> 3] = p0;
                p_s[warp][1][lane >> 3] = p1;
            }
            __syncwarp();

            float4 pq0 = *(const float4*)&p_s[warp][0][0];
            float4 pq1 = *(const float4*)&p_s[warp][1][0];
            unsigned long long pd;
            pd = pk2(pq0.x, pq0.x); FMA2(s2[0], cxy0, pd); FMA2(s2[1], czw0, pd);
            pd = pk2(pq0.y, pq0.y); FMA2(s2[2], cxy0, pd); FMA2(s2[3], czw0, pd);
            pd = pk2(pq0.z, pq0.z); FMA2(s2[4], cxy0, pd); FMA2(s2[5], czw0, pd);
            pd = pk2(pq0.w, pq0.w); FMA2(s2[6], cxy0, pd); FMA2(s2[7], czw0, pd);
            pd = pk2(pq1.x, pq1.x); FMA2(s2[0], cxy1, pd); FMA2(s2[1], czw1, pd);
            pd = pk2(pq1.y, pq1.y); FMA2(s2[2], cxy1, pd); FMA2(s2[3], czw1, pd);
            pd = pk2(pq1.z, pq1.z); FMA2(s2[4], cxy1, pd); FMA2(s2[5], czw1, pd);
            pd = pk2(pq1.w, pq1.w); FMA2(s2[6], cxy1, pd); FMA2(s2[7], czw1, pd);
        }

        __syncthreads();
        if (t + 2 < ns) {
            load_stage(t + 2);
            asm volatile("cp.async.commit_group;");
        }
    }

    // combine: heads h<4 from warps 0-3, h>=4 from warps 4-7
    __shared__ float sm[8 * 4 * 128];    // 16 KB
    __shared__ float sl[8][4];
    #pragma unroll
    for (int hh = 0; hh < 4; hh++) {
        float2 e01 = upk2(s2[2 * hh]);
        float2 e23 = upk2(s2[2 * hh + 1]);
        *(float4*)&sm[warp * 512 + hh * 128 + lane * 4] =
            make_float4(e01.x, e01.y, e23.x, e23.y);
    }
    if ((lane & 7) == 0) sl[warp][lane >> 3] = l_acc;
    __syncthreads();

    const size_t base = (size_t)bp * 8 * E_;
    #pragma unroll
    for (int k = 0; k < 4; k++) {
        int idx = tid + k * 256;
        int hh = idx >> 7, e = idx & 127;
        int w0 = (hh >> 2) * 4, hi = hh & 3;
        float a = 0.0f;
        #pragma unroll
        for (int w = 0; w < 4; w++) a += sm[(w0 + w) * 512 + hi * 128 + e];
        g_ps[base + idx] = a;
    }
    if (tid < 8) {
        int w0 = (tid >> 2) * 4, hi = tid & 3;
        float a = 0.0f;
        #pragma unroll
        for (int w = 0; w < 4; w++) a += sl[w0 + w][hi];
        g_pl[bp * 8 + tid] = a;
    }
}

// ---------------------------------------------------------------------------
// K2: per batch — combine partials -> sbar -> ctx -> dec -> qf -> (w, kb)
// ---------------------------------------------------------------------------
__global__ void __launch_bounds__(128) k_epilogue(
    const float* __restrict__ Vw,  const float* __restrict__ Vb,
    const float* __restrict__ Wow, const float* __restrict__ Wob,
    const float* __restrict__ Qfw, const float* __restrict__ Qfb,
    const float* __restrict__ Kfw, const float* __restrict__ Kfb)
{
    const int b = blockIdx.x, tid = threadIdx.x;
    __shared__ float sbar[1024], ctx[128], dec[128], qf[128], r2[128];
    __shared__ float invl[8];

    if (tid < 8) {
        float L = 0.0f;
        #pragma unroll
        for (int p = 0; p < SPLIT; p++)
            L += g_pl[(b * SPLIT + p) * 8 + tid];
        invl[tid] = 1.0f / L;
    }
    __syncthreads();

    #pragma unroll
    for (int hh = 0; hh < 8; hh++) {
        float a = 0.0f;
        #pragma unroll
        for (int p = 0; p < SPLIT; p++)
            a += g_ps[(size_t)(b * SPLIT + p) * 8 * E_ + hh * E_ + tid];
        sbar[hh * 128 + tid] = a * invl[hh];
    }
    __syncthreads();

    {
        const int head = tid >> 4;
        float a = Vb[tid];
        const float4* wr = (const float4*)(Vw + (size_t)tid * E_);
        const float4* xc = (const float4*)&sbar[head * 128];
        #pragma unroll 8
        for (int i = 0; i < 32; i++) {
            float4 w = wr[i], x = xc[i];
            a += w.x * x.x + w.y * x.y + w.z * x.z + w.w * x.w;
        }
        ctx[tid] = a;
    }
    __syncthreads();
    {
        float a = Wob[tid];
        const float4* wr = (const float4*)(Wow + (size_t)tid * E_);
        const float4* xc = (const float4*)ctx;
        #pragma unroll 8
        for (int i = 0; i < 32; i++) {
            float4 w = wr[i], x = xc[i];
            a += w.x * x.x + w.y * x.y + w.z * x.z + w.w * x.w;
        }
        dec[tid] = a;
    }
    __syncthreads();
    {
        float a = Qfb[tid];
        const float4* wr = (const float4*)(Qfw + (size_t)tid * E_);
        const float4* xc = (const float4*)dec;
        #pragma unroll 8
        for (int i = 0; i < 32; i++) {
            float4 w = wr[i], x = xc[i];
            a += w.x * x.x + w.y * x.y + w.z * x.z + w.w * x.w;
        }
        qf[tid] = a;
    }
    __syncthreads();

    {
        float a = 0.0f;
        #pragma unroll 8
        for (int j = 0; j < 128; j++)
            a += qf[j] * Kfw[(size_t)j * E_ + tid];
        g_w[b * 128 + tid] = a;
    }
    r2[tid] = qf[tid] * Kfb[tid];
    __syncthreads();
    for (int st = 64; st; st >>= 1) {
        if (tid < st) r2[tid] += r2[tid + st];
        __syncthreads();
    }
    if (tid == 0) g_kb[b] = r2[0];
}

// ---------------------------------------------------------------------------
// K3: logits. Masked rows: write -1e8, never touch h. Unmasked: paired fold.
// ---------------------------------------------------------------------------
__global__ void __launch_bounds__(256) k_logits(
    const float* __restrict__ h, const int* __restrict__ mask,
    float* __restrict__ out)
{
    const int b = blockIdx.y, chunk = blockIdx.x;
    const int warp = threadIdx.x >> 5, lane = threadIdx.x & 31;

    float4 w4 = *(const float4*)&g_w[b * 128 + lane * 4];
    float  kb = g_kb[b];

    const int c0 = chunk * 256 + warp * 32;
    const float* rbase = h + ((size_t)b * C_ + c0) * E_ + lane * 4;
    float* ob = out + (size_t)b * C_ + c0;

    const int m = mask[b * C_ + c0 + lane];
    unsigned bits = __ballot_sync(0xffffffffu, m == 0);
    if (m) ob[lane] = -1.0e8f;

    const bool hi = (lane & 16) != 0;

    int i0 = -1, i1 = -1;
    if (bits) { i0 = __ffs(bits) - 1; bits &= bits - 1; }
    if (bits) { i1 = __ffs(bits) - 1; bits &= bits - 1; }
    float4 A0 = make_float4(0.f, 0.f, 0.f, 0.f), A1 = A0;
    if (i0 >= 0) {
        A0 = *(const float4*)(rbase + (size_t)i0 * E_);
        A1 = *(const float4*)(rbase + (size_t)(i1 >= 0 ? i1 : i0) * E_);
    }

    while (i0 >= 0) {
        int n0 = -1, n1 = -1;
        if (bits) { n0 = __ffs(bits) - 1; bits &= bits - 1; }
        if (bits) { n1 = __ffs(bits) - 1; bits &= bits - 1; }
        float4 N0, N1;
        if (n0 >= 0) {
            N0 = *(const float4*)(rbase + (size_t)n0 * E_);
            N1 = *(const float4*)(rbase + (size_t)(n1 >= 0 ? n1 : n0) * E_);
        }

        float p0 = A0.x * w4.x + A0.y * w4.y + A0.z * w4.z + A0.w * w4.w;
        float p1 = A1.x * w4.x + A1.y * w4.y + A1.z * w4.z + A1.w * w4.w;

        float send = hi ? p0 : p1;
        float keep = hi ? p1 : p0;
        float t = keep + __shfl_xor_sync(0xffffffffu, send, 16);
        t += __shfl_xor_sync(0xffffffffu, t, 8);
        t += __shfl_xor_sync(0xffffffffu, t, 4);
        t += __shfl_xor_sync(0xffffffffu, t, 2);
        t += __shfl_xor_sync(0xffffffffu, t, 1);

        float lg = (t + kb) * 0.08838834764831845f;   // 1/sqrt(128)
        float val = 10.0f * tanhf(lg);
        if (lane == 0)                  ob[i0] = val;
        else if (lane == 16 && i1 >= 0) ob[i1] = val;

        i0 = n0; i1 = n1; A0 = N0; A1 = N1;
    }
}

// ---------------------------------------------------------------------------
extern "C" void kernel_launch(void* const* d_in, const int* in_sizes, int n_in,
                              void* d_out, int out_size) {
    const float* h    = (const float*)d_in[0];
    const float* hN   = (const float*)d_in[1];
    const float* hpr  = (const float*)d_in[2];
    const float* h0   = (const float*)d_in[3];
    const int*   mask = (const int*)  d_in[4];
    const float* Qw   = (const float*)d_in[5];
    const float* Qb   = (const float*)d_in[6];
    const float* Vw   = (const float*)d_in[7];
    const float* Vb   = (const float*)d_in[8];
    const float* Wow  = (const float*)d_in[9];
    const float* Wob  = (const float*)d_in[10];
    const float* Qfw  = (const float*)d_in[11];
    const float* Qfb  = (const float*)d_in[12];
    const float* Kfw  = (const float*)d_in[13];
    const float* Kfb  = (const float*)d_in[14];
    float* out = (float*)d_out;

    const int DSMEM = 2 * TROWS * E_ * (int)sizeof(float);   // 64 KB
    cudaFuncSetAttribute(k_fused, cudaFuncAttributeMaxDynamicSharedMemorySize, DSMEM);

    k_compact <<<dim3(SPLIT, B_), 256>>>(mask);
    k_prep    <<<B_, 128>>>(hN, hpr, h0, Qw, Qb, Vw, Vb);
    k_fused   <<<dim3(SPLIT, B_), 256, DSMEM>>>(h);
    k_epilogue<<<B_, 128>>>(Vw, Vb, Wow, Wob, Qfw, Qfb, Kfw, Kfb);
    k_logits  <<<dim3(4, B_), 256>>>(h, mask, out);
}

// round 15
// speedup vs baseline: 1.5885x; 1.1881x over previous
#include <cuda_runtime.h>
#include <math.h>
#include <stdint.h>

#define B_    1024
#define C_    1024
#define E_    128
#define SPLIT 4
#define RPB   (C_ / SPLIT)    // 256 rows per fused block
#define TROWS 64              // compacted rows per pipeline stage (32KB)

// ---------------- device scratch (allocation-free rule) ----------------
__device__ float g_u [B_ * 8 * E_];
__device__ float g_qb[B_ * 8];
__device__ float g_pl[B_ * SPLIT * 8];
__device__ float g_ps[(size_t)B_ * SPLIT * 8 * E_];
__device__ float g_w [B_ * E_];
__device__ float g_kb[B_];
__device__ int   g_cidx[B_ * SPLIT * RPB];
__device__ int   g_cnt [B_ * SPLIT];
__device__ float g_VwT [E_ * E_];     // [k][j] transposed weights
__device__ float g_WowT[E_ * E_];
__device__ float g_QfwT[E_ * E_];
__device__ float g_QwT [384 * E_];

// ---------------- f32x2 helpers ----------------
__device__ __forceinline__ unsigned long long pk2(float x, float y) {
    unsigned long long r;
    asm("mov.b64 %0, {%1, %2};" : "=l"(r) : "f"(x), "f"(y));
    return r;
}
__device__ __forceinline__ float2 upk2(unsigned long long v) {
    float2 r;
    asm("mov.b64 {%0, %1}, %2;" : "=f"(r.x), "=f"(r.y) : "l"(v));
    return r;
}
#define MUL2(d, a, b) asm("mul.rn.f32x2 %0, %1, %2;" : "=l"(d) : "l"(a), "l"(b))
#define FMA2(d, a, b) asm("fma.rn.f32x2 %0, %1, %2, %0;" : "+l"(d) : "l"(a), "l"(b))

__device__ __forceinline__ void cp16(unsigned int dst, const void* src) {
    asm volatile("cp.async.cg.shared.global [%0], [%1], 16;" :: "r"(dst), "l"(src));
}

// ---------------------------------------------------------------------------
// K-transpose: WT[k][j] = W[j][k] for Vw, Wow, Qfw (128x128) and Qw (128x384).
// ---------------------------------------------------------------------------
__global__ void __launch_bounds__(256) k_transpose(
    const float* __restrict__ Vw, const float* __restrict__ Wow,
    const float* __restrict__ Qfw, const float* __restrict__ Qw)
{
    int i = blockIdx.x * 256 + threadIdx.x;
    if (blockIdx.y == 3) {
        if (i < 384 * E_) g_QwT[i] = Qw[(i & 127) * 384 + (i >> 7)];
        return;
    }
    if (i >= E_ * E_) return;
    const float* src = blockIdx.y == 0 ? Vw : (blockIdx.y == 1 ? Wow : Qfw);
    float*       dst = blockIdx.y == 0 ? g_VwT : (blockIdx.y == 1 ? g_WowT : g_QfwT);
    dst[i] = src[(i & 127) * E_ + (i >> 7)];
}

// ---------------------------------------------------------------------------
// K-compact: per (b, part): list of unmasked rows + count.
// ---------------------------------------------------------------------------
__global__ void __launch_bounds__(256) k_compact(const int* __restrict__ mask)
{
    const int bp = blockIdx.y * SPLIT + blockIdx.x;
    const int tid = threadIdx.x, warp = tid >> 5, lane = tid & 31;

    __shared__ int wcnt[8], woff[8];

    int m = mask[blockIdx.y * C_ + blockIdx.x * RPB + tid];
    unsigned bal = __ballot_sync(0xffffffffu, m == 0);
    int pin = __popc(bal & ((1u << lane) - 1));
    if (lane == 0) wcnt[warp] = __popc(bal);
    __syncthreads();
    if (tid < 8) {
        int o = 0;
        for (int w = 0; w < tid; w++) o += wcnt[w];
        woff[tid] = o;
    }
    __syncthreads();
    if (m == 0) g_cidx[bp * RPB + woff[warp] + pin] = tid;
    if (tid == 255) g_cnt[bp] = woff[7] + wcnt[7];
}

// ---------------------------------------------------------------------------
// K0: per batch — q = Qw@hc + Qb (coalesced via QwT);  u, qb.
// ---------------------------------------------------------------------------
__global__ void __launch_bounds__(128) k_prep(
    const float* __restrict__ hN, const float* __restrict__ hpr,
    const float* __restrict__ h0,
    const float* __restrict__ Qb,
    const float* __restrict__ Vw, const float* __restrict__ Vb)
{
    const int b = blockIdx.x, tid = threadIdx.x;
    __shared__ float hc_s[384];
    __shared__ float q_s[128];

    hc_s[tid]       = hN [b * E_ + tid];
    hc_s[128 + tid] = hpr[b * E_ + tid];
    hc_s[256 + tid] = h0 [b * E_ + tid];
    __syncthreads();

    {
        float a0 = Qb[tid], a1 = 0.f, a2 = 0.f, a3 = 0.f;
        #pragma unroll 8
        for (int k = 0; k < 384; k += 4) {
            a0 += g_QwT[(k + 0) * 128 + tid] * hc_s[k + 0];
            a1 += g_QwT[(k + 1) * 128 + tid] * hc_s[k + 1];
            a2 += g_QwT[(k + 2) * 128 + tid] * hc_s[k + 2];
            a3 += g_QwT[(k + 3) * 128 + tid] * hc_s[k + 3];
        }
        q_s[tid] = (a0 + a1) + (a2 + a3);
    }
    __syncthreads();

    const int k = tid;
    #pragma unroll
    for (int hh = 0; hh < 8; hh++) {
        float acc = 0.0f;
        #pragma unroll
        for (int j = 0; j < 16; j++)
            acc += q_s[hh * 16 + j] * Vw[(size_t)(hh * 16 + j) * E_ + k];
        g_u[((size_t)b * 8 + hh) * E_ + k] = 0.25f * acc;
    }
    if (tid < 8) {
        float a = 0.0f;
        #pragma unroll
        for (int j = 0; j < 16; j++)
            a += q_s[tid * 16 + j] * Vb[tid * 16 + j];
        g_qb[b * 8 + tid] = 0.25f * a;
    }
}

// ---------------------------------------------------------------------------
// K1: compacted cp.async pipeline — only unmasked rows are ever loaded.
// ---------------------------------------------------------------------------
__global__ void __launch_bounds__(256, 2) k_fused(const float* __restrict__ h)
{
    const int b = blockIdx.y, part = blockIdx.x;
    const int bp = b * SPLIT + part;
    const int tid = threadIdx.x, warp = tid >> 5, lane = tid & 31;
    const int hg = warp >> 2;
    const int ws = warp & 3;

    extern __shared__ float hbuf[];            // 2 stages x 8192 floats (64KB)
    __shared__ int   cidx_s[RPB];
    __shared__ float p_s[8][2][4];

    const float* hb = h + (size_t)b * C_ * E_ + (size_t)part * RPB * E_;

    const int nU = g_cnt[bp];
    const int ns = (nU + TROWS - 1) / TROWS;
    cidx_s[tid] = g_cidx[bp * RPB + tid];
    __syncthreads();

    auto load_stage = [&](int t) {
        float* dst = hbuf + (t & 1) * 8192;
        #pragma unroll
        for (int k = 0; k < 8; k++) {
            int idx = k * 256 + tid;
            int i = t * TROWS + (idx >> 5);
            int j = idx & 31;
            if (i < nU) {
                unsigned int d = (unsigned int)__cvta_generic_to_shared(
                    dst + (idx >> 5) * 128 + j * 4);
                cp16(d, hb + (size_t)cidx_s[i] * E_ + j * 4);
            }
        }
    };

    load_stage(0);
    asm volatile("cp.async.commit_group;");
    load_stage(1);
    asm volatile("cp.async.commit_group;");

    unsigned long long u01[4], u23[4];
    #pragma unroll
    for (int hh = 0; hh < 4; hh++) {
        float4 uu = *(const float4*)&g_u[((size_t)b * 8 + hg * 4 + hh) * E_ + lane * 4];
        u01[hh] = pk2(uu.x, uu.y);
        u23[hh] = pk2(uu.z, uu.w);
    }
    const float qbr = g_qb[b * 8 + hg * 4 + (lane >> 3)];

    unsigned long long s2[8];
    #pragma unroll
    for (int i = 0; i < 8; i++) s2[i] = pk2(0.f, 0.f);
    float l_acc = 0.0f;

    const bool hi4 = (lane & 16) != 0;
    const bool hi3 = (lane & 8)  != 0;

    #pragma unroll 1
    for (int t = 0; t < ns; t++) {
        if (t == ns - 1) asm volatile("cp.async.wait_group 0;");
        else             asm volatile("cp.async.wait_group 1;");
        __syncthreads();

        const float* hs = hbuf + (t & 1) * 8192;
        int cnt_s = nU - t * TROWS;
        if (cnt_s > TROWS) cnt_s = TROWS;

        #pragma unroll 1
        for (int i = 0; ws + 8 * i < cnt_s; i++) {
            const int r0 = ws + 8 * i;
            int r1 = r0 + 4; float v1 = 1.0f;
            if (r1 >= cnt_s) { r1 = r0; v1 = 0.0f; }

            float4 c0 = *(const float4*)&hs[r0 * 128 + lane * 4];
            float4 c1 = *(const float4*)&hs[r1 * 128 + lane * 4];
            unsigned long long cxy0 = pk2(c0.x, c0.y), czw0 = pk2(c0.z, c0.w);
            unsigned long long cxy1 = pk2(c1.x, c1.y), czw1 = pk2(c1.z, c1.w);

            float d[2][4];
            #pragma unroll
            for (int hh = 0; hh < 4; hh++) {
                unsigned long long t0, t1;
                MUL2(t0, cxy0, u01[hh]); FMA2(t0, czw0, u23[hh]);
                MUL2(t1, cxy1, u01[hh]); FMA2(t1, czw1, u23[hh]);
                float2 a0 = upk2(t0), a1 = upk2(t1);
                d[0][hh] = a0.x + a0.y;
                d[1][hh] = a1.x + a1.y;
            }

            #pragma unroll
            for (int j = 0; j < 2; j++)
                #pragma unroll
                for (int q = 0; q < 2; q++) {
                    float send = hi4 ? d[j][q] : d[j][q + 2];
                    float keep = hi4 ? d[j][q + 2] : d[j][q];
                    d[j][q] = keep + __shfl_xor_sync(0xffffffffu, send, 16);
                }
            float dd[2];
            #pragma unroll
            for (int j = 0; j < 2; j++) {
                float send = hi3 ? d[j][0] : d[j][1];
                float keep = hi3 ? d[j][1] : d[j][0];
                dd[j] = keep + __shfl_xor_sync(0xffffffffu, send, 8);
            }
            #pragma unroll
            for (int j = 0; j < 2; j++)
                dd[j] += __shfl_xor_sync(0xffffffffu, dd[j], 4);
            #pragma unroll
            for (int j = 0; j < 2; j++)
                dd[j] += __shfl_xor_sync(0xffffffffu, dd[j], 2);
            #pragma unroll
            for (int j = 0; j < 2; j++)
                dd[j] += __shfl_xor_sync(0xffffffffu, dd[j], 1);

            float p0 = __expf(dd[0] + qbr);
            float p1 = __expf(dd[1] + qbr) * v1;
            l_acc += p0 + p1;

            __syncwarp();
            if ((lane & 7) == 0) {
                p_s[warp][0][lane >> 3] = p0;
                p_s[warp][1][lane >> 3] = p1;
            }
            __syncwarp();

            float4 pq0 = *(const float4*)&p_s[warp][0][0];
            float4 pq1 = *(const float4*)&p_s[warp][1][0];
            unsigned long long pd;
            pd = pk2(pq0.x, pq0.x); FMA2(s2[0], cxy0, pd); FMA2(s2[1], czw0, pd);
            pd = pk2(pq0.y, pq0.y); FMA2(s2[2], cxy0, pd); FMA2(s2[3], czw0, pd);
            pd = pk2(pq0.z, pq0.z); FMA2(s2[4], cxy0, pd); FMA2(s2[5], czw0, pd);
            pd = pk2(pq0.w, pq0.w); FMA2(s2[6], cxy0, pd); FMA2(s2[7], czw0, pd);
            pd = pk2(pq1.x, pq1.x); FMA2(s2[0], cxy1, pd); FMA2(s2[1], czw1, pd);
            pd = pk2(pq1.y, pq1.y); FMA2(s2[2], cxy1, pd); FMA2(s2[3], czw1, pd);
            pd = pk2(pq1.z, pq1.z); FMA2(s2[4], cxy1, pd); FMA2(s2[5], czw1, pd);
            pd = pk2(pq1.w, pq1.w); FMA2(s2[6], cxy1, pd); FMA2(s2[7], czw1, pd);
        }

        __syncthreads();
        if (t + 2 < ns) {
            load_stage(t + 2);
            asm volatile("cp.async.commit_group;");
        }
    }

    __shared__ float sm[8 * 4 * 128];
    __shared__ float sl[8][4];
    #pragma unroll
    for (int hh = 0; hh < 4; hh++) {
        float2 e01 = upk2(s2[2 * hh]);
        float2 e23 = upk2(s2[2 * hh + 1]);
        *(float4*)&sm[warp * 512 + hh * 128 + lane * 4] =
            make_float4(e01.x, e01.y, e23.x, e23.y);
    }
    if ((lane & 7) == 0) sl[warp][lane >> 3] = l_acc;
    __syncthreads();

    const size_t base = (size_t)bp * 8 * E_;
    #pragma unroll
    for (int k = 0; k < 4; k++) {
        int idx = tid + k * 256;
        int hh = idx >> 7, e = idx & 127;
        int w0 = (hh >> 2) * 4, hi = hh & 3;
        float a = 0.0f;
        #pragma unroll
        for (int w = 0; w < 4; w++) a += sm[(w0 + w) * 512 + hi * 128 + e];
        g_ps[base + idx] = a;
    }
    if (tid < 8) {
        int w0 = (tid >> 2) * 4, hi = tid & 3;
        float a = 0.0f;
        #pragma unroll
        for (int w = 0; w < 4; w++) a += sl[w0 + w][hi];
        g_pl[bp * 8 + tid] = a;
    }
}

// ---------------------------------------------------------------------------
// K2: per batch — combine -> sbar -> ctx -> dec -> qf -> (w, kb).
//     All matvecs via transposed weights: coalesced, L1-resident.
// ---------------------------------------------------------------------------
__global__ void __launch_bounds__(128) k_epilogue(
    const float* __restrict__ Vb,  const float* __restrict__ Wob,
    const float* __restrict__ Qfb,
    const float* __restrict__ Kfw, const float* __restrict__ Kfb)
{
    const int b = blockIdx.x, tid = threadIdx.x;
    __shared__ float sbar[8 * 132];       // padded stride vs bank conflicts
    __shared__ float ctx[128], dec[128], qf[128], r2[128];
    __shared__ float invl[8];

    if (tid < 8) {
        float L = 0.0f;
        #pragma unroll
        for (int p = 0; p < SPLIT; p++)
            L += g_pl[(b * SPLIT + p) * 8 + tid];
        invl[tid] = 1.0f / L;
    }
    __syncthreads();

    #pragma unroll
    for (int hh = 0; hh < 8; hh++) {
        float a = 0.0f;
        #pragma unroll
        for (int p = 0; p < SPLIT; p++)
            a += g_ps[(size_t)(b * SPLIT + p) * 8 * E_ + hh * E_ + tid];
        sbar[hh * 132 + tid] = a * invl[hh];
    }
    __syncthreads();

    {   // ctx[j] = Vb[j] + sum_k VwT[k][j] * sbar[head(j)][k]
        const int hb_ = (tid >> 4) * 132;
        float a0 = Vb[tid], a1 = 0.f, a2 = 0.f, a3 = 0.f;
        #pragma unroll 8
        for (int k = 0; k < 128; k += 4) {
            a0 += g_VwT[(k + 0) * 128 + tid] * sbar[hb_ + k + 0];
            a1 += g_VwT[(k + 1) * 128 + tid] * sbar[hb_ + k + 1];
            a2 += g_VwT[(k + 2) * 128 + tid] * sbar[hb_ + k + 2];
            a3 += g_VwT[(k + 3) * 128 + tid] * sbar[hb_ + k + 3];
        }
        ctx[tid] = (a0 + a1) + (a2 + a3);
    }
    __syncthreads();
    {   // dec = WowT^T ctx + Wob
        float a0 = Wob[tid], a1 = 0.f, a2 = 0.f, a3 = 0.f;
        #pragma unroll 8
        for (int k = 0; k < 128; k += 4) {
            a0 += g_WowT[(k + 0) * 128 + tid] * ctx[k + 0];
            a1 += g_WowT[(k + 1) * 128 + tid] * ctx[k + 1];
            a2 += g_WowT[(k + 2) * 128 + tid] * ctx[k + 2];
            a3 += g_WowT[(k + 3) * 128 + tid] * ctx[k + 3];
        }
        dec[tid] = (a0 + a1) + (a2 + a3);
    }
    __syncthreads();
    {   // qf = QfwT^T dec + Qfb
        float a0 = Qfb[tid], a1 = 0.f, a2 = 0.f, a3 = 0.f;
        #pragma unroll 8
        for (int k = 0; k < 128; k += 4) {
            a0 += g_QfwT[(k + 0) * 128 + tid] * dec[k + 0];
            a1 += g_QfwT[(k + 1) * 128 + tid] * dec[k + 1];
            a2 += g_QfwT[(k + 2) * 128 + tid] * dec[k + 2];
            a3 += g_QfwT[(k + 3) * 128 + tid] * dec[k + 3];
        }
        qf[tid] = (a0 + a1) + (a2 + a3);
    }
    __syncthreads();

    {   // w[k] = sum_j qf[j] * Kfw[j][k]   (already coalesced over tid=k)
        float a0 = 0.f, a1 = 0.f, a2 = 0.f, a3 = 0.f;
        #pragma unroll 8
        for (int j = 0; j < 128; j += 4) {
            a0 += qf[j + 0] * Kfw[(size_t)(j + 0) * E_ + tid];
            a1 += qf[j + 1] * Kfw[(size_t)(j + 1) * E_ + tid];
            a2 += qf[j + 2] * Kfw[(size_t)(j + 2) * E_ + tid];
            a3 += qf[j + 3] * Kfw[(size_t)(j + 3) * E_ + tid];
        }
        g_w[b * 128 + tid] = (a0 + a1) + (a2 + a3);
    }
    r2[tid] = qf[tid] * Kfb[tid];
    __syncthreads();
    for (int st = 64; st; st >>= 1) {
        if (tid < st) r2[tid] += r2[tid + st];
        __syncthreads();
    }
    if (tid == 0) g_kb[b] = r2[0];
}

// ---------------------------------------------------------------------------
// K3: logits. Masked rows: write -1e8, never touch h. Unmasked: paired fold.
// ---------------------------------------------------------------------------
__global__ void __launch_bounds__(256) k_logits(
    const float* __restrict__ h, const int* __restrict__ mask,
    float* __restrict__ out)
{
    const int b = blockIdx.y, chunk = blockIdx.x;
    const int warp = threadIdx.x >> 5, lane = threadIdx.x & 31;

    float4 w4 = *(const float4*)&g_w[b * 128 + lane * 4];
    float  kb = g_kb[b];

    const int c0 = chunk * 256 + warp * 32;
    const float* rbase = h + ((size_t)b * C_ + c0) * E_ + lane * 4;
    float* ob = out + (size_t)b * C_ + c0;

    const int m = mask[b * C_ + c0 + lane];
    unsigned bits = __ballot_sync(0xffffffffu, m == 0);
    if (m) ob[lane] = -1.0e8f;

    const bool hi = (lane & 16) != 0;

    int i0 = -1, i1 = -1;
    if (bits) { i0 = __ffs(bits) - 1; bits &= bits - 1; }
    if (bits) { i1 = __ffs(bits) - 1; bits &= bits - 1; }
    float4 A0 = make_float4(0.f, 0.f, 0.f, 0.f), A1 = A0;
    if (i0 >= 0) {
        A0 = *(const float4*)(rbase + (size_t)i0 * E_);
        A1 = *(const float4*)(rbase + (size_t)(i1 >= 0 ? i1 : i0) * E_);
    }

    while (i0 >= 0) {
        int n0 = -1, n1 = -1;
        if (bits) { n0 = __ffs(bits) - 1; bits &= bits - 1; }
        if (bits) { n1 = __ffs(bits) - 1; bits &= bits - 1; }
        float4 N0, N1;
        if (n0 >= 0) {
            N0 = *(const float4*)(rbase + (size_t)n0 * E_);
            N1 = *(const float4*)(rbase + (size_t)(n1 >= 0 ? n1 : n0) * E_);
        }

        float p0 = A0.x * w4.x + A0.y * w4.y + A0.z * w4.z + A0.w * w4.w;
        float p1 = A1.x * w4.x + A1.y * w4.y + A1.z * w4.z + A1.w * w4.w;

        float send = hi ? p0 : p1;
        float keep = hi ? p1 : p0;
        float t = keep + __shfl_xor_sync(0xffffffffu, send, 16);
        t += __shfl_xor_sync(0xffffffffu, t, 8);
        t += __shfl_xor_sync(0xffffffffu, t, 4);
        t += __shfl_xor_sync(0xffffffffu, t, 2);
        t += __shfl_xor_sync(0xffffffffu, t, 1);

        float lg = (t + kb) * 0.08838834764831845f;
        float val = 10.0f * tanhf(lg);
        if (lane == 0)                  ob[i0] = val;
        else if (lane == 16 && i1 >= 0) ob[i1] = val;

        i0 = n0; i1 = n1; A0 = N0; A1 = N1;
    }
}

// ---------------------------------------------------------------------------
extern "C" void kernel_launch(void* const* d_in, const int* in_sizes, int n_in,
                              void* d_out, int out_size) {
    const float* h    = (const float*)d_in[0];
    const float* hN   = (const float*)d_in[1];
    const float* hpr  = (const float*)d_in[2];
    const float* h0   = (const float*)d_in[3];
    const int*   mask = (const int*)  d_in[4];
    const float* Qw   = (const float*)d_in[5];
    const float* Qb   = (const float*)d_in[6];
    const float* Vw   = (const float*)d_in[7];
    const float* Vb   = (const float*)d_in[8];
    const float* Wow  = (const float*)d_in[9];
    const float* Wob  = (const float*)d_in[10];
    const float* Qfw  = (const float*)d_in[11];
    const float* Qfb  = (const float*)d_in[12];
    const float* Kfw  = (const float*)d_in[13];
    const float* Kfb  = (const float*)d_in[14];
    float* out = (float*)d_out;

    const int DSMEM = 2 * TROWS * E_ * (int)sizeof(float);   // 64 KB
    cudaFuncSetAttribute(k_fused, cudaFuncAttributeMaxDynamicSharedMemorySize, DSMEM);

    k_transpose<<<dim3(192, 4), 256>>>(Vw, Wow, Qfw, Qw);
    k_compact  <<<dim3(SPLIT, B_), 256>>>(mask);
    k_prep     <<<B_, 128>>>(hN, hpr, h0, Qb, Vw, Vb);
    k_fused    <<<dim3(SPLIT, B_), 256, DSMEM>>>(h);
    k_epilogue <<<B_, 128>>>(Vb, Wob, Qfb, Kfw, Kfb);
    k_logits   <<<dim3(4, B_), 256>>>(h, mask, out);
}

// round 16
// speedup vs baseline: 1.6655x; 1.0484x over previous
#include <cuda_runtime.h>
#include <math.h>
#include <stdint.h>

#define B_    1024
#define C_    1024
#define E_    128
#define SPLIT 4
#define RPB   (C_ / SPLIT)    // 256 rows per fused block
#define TROWS 64              // compacted rows per pipeline stage (32KB)

// ---------------- device scratch (allocation-free rule) ----------------
__device__ float g_u [B_ * 8 * E_];
__device__ float g_qb[B_ * 8];
__device__ float g_pl[B_ * SPLIT * 8];
__device__ float g_ps[(size_t)B_ * SPLIT * 8 * E_];
__device__ float g_w [B_ * E_];
__device__ float g_kb[B_];
__device__ int   g_cidx[B_ * SPLIT * RPB];
__device__ int   g_cnt [B_ * SPLIT];
__device__ float g_VwT [E_ * E_];
__device__ float g_WowT[E_ * E_];
__device__ float g_QfwT[E_ * E_];
__device__ float g_QwT [384 * E_];

// ---------------- f32x2 helpers ----------------
__device__ __forceinline__ unsigned long long pk2(float x, float y) {
    unsigned long long r;
    asm("mov.b64 %0, {%1, %2};" : "=l"(r) : "f"(x), "f"(y));
    return r;
}
__device__ __forceinline__ float2 upk2(unsigned long long v) {
    float2 r;
    asm("mov.b64 {%0, %1}, %2;" : "=f"(r.x), "=f"(r.y) : "l"(v));
    return r;
}
#define MUL2(d, a, b) asm("mul.rn.f32x2 %0, %1, %2;" : "=l"(d) : "l"(a), "l"(b))
#define FMA2(d, a, b) asm("fma.rn.f32x2 %0, %1, %2, %0;" : "+l"(d) : "l"(a), "l"(b))

__device__ __forceinline__ void cp16(unsigned int dst, const void* src) {
    asm volatile("cp.async.cg.shared.global [%0], [%1], 16;" :: "r"(dst), "l"(src));
}

// ---------------------------------------------------------------------------
// K-setup: compact (all 4096 blocks) + weight transposes (first 384 blocks).
// ---------------------------------------------------------------------------
__global__ void __launch_bounds__(256) k_setup(
    const int* __restrict__ mask,
    const float* __restrict__ Vw, const float* __restrict__ Wow,
    const float* __restrict__ Qfw, const float* __restrict__ Qw)
{
    const int bp = blockIdx.y * SPLIT + blockIdx.x;
    const int tid = threadIdx.x, warp = tid >> 5, lane = tid & 31;

    __shared__ int wcnt[8], woff[8];

    int m = mask[blockIdx.y * C_ + blockIdx.x * RPB + tid];
    unsigned bal = __ballot_sync(0xffffffffu, m == 0);
    int pin = __popc(bal & ((1u << lane) - 1));
    if (lane == 0) wcnt[warp] = __popc(bal);
    __syncthreads();
    if (tid < 8) {
        int o = 0;
        for (int w = 0; w < tid; w++) o += wcnt[w];
        woff[tid] = o;
    }
    __syncthreads();
    if (m == 0) g_cidx[bp * RPB + woff[warp] + pin] = tid;
    if (tid == 255) g_cnt[bp] = woff[7] + wcnt[7];

    // fold weight transposes into the first 384 blocks
    if (bp < 192) {
        int sel = bp >> 6;                       // 0..2
        int i = (bp & 63) * 256 + tid;           // 0..16383
        const float* src = sel == 0 ? Vw : (sel == 1 ? Wow : Qfw);
        float*       dst = sel == 0 ? g_VwT : (sel == 1 ? g_WowT : g_QfwT);
        dst[i] = src[(i & 127) * E_ + (i >> 7)];
    } else if (bp < 384) {
        int i = (bp - 192) * 256 + tid;          // 0..49151
        g_QwT[i] = Qw[(i & 127) * 384 + (i >> 7)];
    }
}

// ---------------------------------------------------------------------------
// K0: per batch — q = QwT^T hc + Qb (coalesced);  u, qb.
// ---------------------------------------------------------------------------
__global__ void __launch_bounds__(128) k_prep(
    const float* __restrict__ hN, const float* __restrict__ hpr,
    const float* __restrict__ h0,
    const float* __restrict__ Qb,
    const float* __restrict__ Vw, const float* __restrict__ Vb)
{
    const int b = blockIdx.x, tid = threadIdx.x;
    __shared__ float hc_s[384];
    __shared__ float q_s[128];

    hc_s[tid]       = hN [b * E_ + tid];
    hc_s[128 + tid] = hpr[b * E_ + tid];
    hc_s[256 + tid] = h0 [b * E_ + tid];
    __syncthreads();

    {
        float a0 = Qb[tid], a1 = 0.f, a2 = 0.f, a3 = 0.f;
        #pragma unroll 8
        for (int k = 0; k < 384; k += 4) {
            a0 += g_QwT[(k + 0) * 128 + tid] * hc_s[k + 0];
            a1 += g_QwT[(k + 1) * 128 + tid] * hc_s[k + 1];
            a2 += g_QwT[(k + 2) * 128 + tid] * hc_s[k + 2];
            a3 += g_QwT[(k + 3) * 128 + tid] * hc_s[k + 3];
        }
        q_s[tid] = (a0 + a1) + (a2 + a3);
    }
    __syncthreads();

    const int k = tid;
    #pragma unroll
    for (int hh = 0; hh < 8; hh++) {
        float acc = 0.0f;
        #pragma unroll
        for (int j = 0; j < 16; j++)
            acc += q_s[hh * 16 + j] * Vw[(size_t)(hh * 16 + j) * E_ + k];
        g_u[((size_t)b * 8 + hh) * E_ + k] = 0.25f * acc;
    }
    if (tid < 8) {
        float a = 0.0f;
        #pragma unroll
        for (int j = 0; j < 16; j++)
            a += q_s[tid * 16 + j] * Vb[tid * 16 + j];
        g_qb[b * 8 + tid] = 0.25f * a;
    }
}

// ---------------------------------------------------------------------------
// K1: compacted cp.async pipeline; 4-row ILP groups; ulonglong2 tile loads.
// ---------------------------------------------------------------------------
__global__ void __launch_bounds__(256, 2) k_fused(const float* __restrict__ h)
{
    const int b = blockIdx.y, part = blockIdx.x;
    const int bp = b * SPLIT + part;
    const int tid = threadIdx.x, warp = tid >> 5, lane = tid & 31;
    const int hg = warp >> 2;       // head group: heads hg*4 .. hg*4+3
    const int ws = warp & 3;        // row stream within stage

    extern __shared__ float hbuf[];            // 2 stages x 8192 floats (64KB)
    __shared__ int   cidx_s[RPB];
    __shared__ float p_s[8][4][4];
    __shared__ float sl[8][4];

    const float* hb = h + (size_t)b * C_ * E_ + (size_t)part * RPB * E_;

    const int nU = g_cnt[bp];
    const int ns = (nU + TROWS - 1) / TROWS;
    cidx_s[tid] = g_cidx[bp * RPB + tid];
    __syncthreads();

    auto load_stage = [&](int t) {
        float* dst = hbuf + (t & 1) * 8192;
        #pragma unroll
        for (int k = 0; k < 8; k++) {
            int idx = k * 256 + tid;
            int i = t * TROWS + (idx >> 5);
            int j = idx & 31;
            if (i < nU) {
                unsigned int d = (unsigned int)__cvta_generic_to_shared(
                    dst + (idx >> 5) * 128 + j * 4);
                cp16(d, hb + (size_t)cidx_s[i] * E_ + j * 4);
            }
        }
    };

    load_stage(0);
    asm volatile("cp.async.commit_group;");
    load_stage(1);
    asm volatile("cp.async.commit_group;");

    unsigned long long u01[4], u23[4];
    #pragma unroll
    for (int hh = 0; hh < 4; hh++) {
        float4 uu = *(const float4*)&g_u[((size_t)b * 8 + hg * 4 + hh) * E_ + lane * 4];
        u01[hh] = pk2(uu.x, uu.y);
        u23[hh] = pk2(uu.z, uu.w);
    }
    const float qbr = g_qb[b * 8 + hg * 4 + (lane >> 3)];

    unsigned long long s2[8];
    #pragma unroll
    for (int i = 0; i < 8; i++) s2[i] = pk2(0.f, 0.f);
    float l_acc = 0.0f;

    const bool hi4 = (lane & 16) != 0;
    const bool hi3 = (lane & 8)  != 0;

    #pragma unroll 1
    for (int t = 0; t < ns; t++) {
        if (t == ns - 1) asm volatile("cp.async.wait_group 0;");
        else             asm volatile("cp.async.wait_group 1;");
        __syncthreads();

        const float* hs = hbuf + (t & 1) * 8192;
        int cnt_s = nU - t * TROWS;
        if (cnt_s > TROWS) cnt_s = TROWS;

        #pragma unroll 1
        for (int g = 0; ws + 16 * g < cnt_s; g++) {
            // 4 rows: ws + 16g + 4j  (dups masked out via v[j])
            ulonglong2 c[4]; float v[4];
            #pragma unroll
            for (int j = 0; j < 4; j++) {
                int r = ws + 16 * g + 4 * j;
                bool ok = r < cnt_s;
                v[j] = ok ? 1.0f : 0.0f;
                int rr = ok ? r : ws + 16 * g;
                c[j] = *(const ulonglong2*)&hs[rr * 128 + lane * 4];
            }

            // dots: 4 rows x 4 heads (packed operands straight from LDS.128)
            float d[4][4];
            #pragma unroll
            for (int j = 0; j < 4; j++)
                #pragma unroll
                for (int hh = 0; hh < 4; hh++) {
                    unsigned long long tt;
                    MUL2(tt, c[j].x, u01[hh]);
                    FMA2(tt, c[j].y, u23[hh]);
                    float2 t2 = upk2(tt);
                    d[j][hh] = t2.x + t2.y;
                }

            // fold level-major across 4 independent rows
            #pragma unroll
            for (int j = 0; j < 4; j++)
                #pragma unroll
                for (int q = 0; q < 2; q++) {
                    float send = hi4 ? d[j][q] : d[j][q + 2];
                    float keep = hi4 ? d[j][q + 2] : d[j][q];
                    d[j][q] = keep + __shfl_xor_sync(0xffffffffu, send, 16);
                }
            float dd[4];
            #pragma unroll
            for (int j = 0; j < 4; j++) {
                float send = hi3 ? d[j][0] : d[j][1];
                float keep = hi3 ? d[j][1] : d[j][0];
                dd[j] = keep + __shfl_xor_sync(0xffffffffu, send, 8);
            }
            #pragma unroll
            for (int j = 0; j < 4; j++)
                dd[j] += __shfl_xor_sync(0xffffffffu, dd[j], 4);
            #pragma unroll
            for (int j = 0; j < 4; j++)
                dd[j] += __shfl_xor_sync(0xffffffffu, dd[j], 2);
            #pragma unroll
            for (int j = 0; j < 4; j++)
                dd[j] += __shfl_xor_sync(0xffffffffu, dd[j], 1);

            float p[4];
            #pragma unroll
            for (int j = 0; j < 4; j++) {
                p[j] = __expf(dd[j] + qbr) * v[j];
                l_acc += p[j];
            }

            __syncwarp();
            if ((lane & 7) == 0) {
                const int k = lane >> 3;
                #pragma unroll
                for (int j = 0; j < 4; j++) p_s[warp][j][k] = p[j];
            }
            __syncwarp();

            #pragma unroll
            for (int j = 0; j < 4; j++) {
                float4 pq = *(const float4*)&p_s[warp][j][0];
                unsigned long long pd;
                pd = pk2(pq.x, pq.x); FMA2(s2[0], c[j].x, pd); FMA2(s2[1], c[j].y, pd);
                pd = pk2(pq.y, pq.y); FMA2(s2[2], c[j].x, pd); FMA2(s2[3], c[j].y, pd);
                pd = pk2(pq.z, pq.z); FMA2(s2[4], c[j].x, pd); FMA2(s2[5], c[j].y, pd);
                pd = pk2(pq.w, pq.w); FMA2(s2[6], c[j].x, pd); FMA2(s2[7], c[j].y, pd);
            }
        }

        __syncthreads();
        if (t + 2 < ns) {
            load_stage(t + 2);
            asm volatile("cp.async.commit_group;");
        }
    }

    // combine: reuse hbuf (all tile reads done) as [warp][head][e] = 16KB
    float* sm = hbuf;
    #pragma unroll
    for (int hh = 0; hh < 4; hh++) {
        float2 e01 = upk2(s2[2 * hh]);
        float2 e23 = upk2(s2[2 * hh + 1]);
        *(float4*)&sm[warp * 512 + hh * 128 + lane * 4] =
            make_float4(e01.x, e01.y, e23.x, e23.y);
    }
    if ((lane & 7) == 0) sl[warp][lane >> 3] = l_acc;
    __syncthreads();

    const size_t base = (size_t)bp * 8 * E_;
    #pragma unroll
    for (int k = 0; k < 4; k++) {
        int idx = tid + k * 256;
        int hh = idx >> 7, e = idx & 127;
        int w0 = (hh >> 2) * 4, hi = hh & 3;
        float a = 0.0f;
        #pragma unroll
        for (int w = 0; w < 4; w++) a += sm[(w0 + w) * 512 + hi * 128 + e];
        g_ps[base + idx] = a;
    }
    if (tid < 8) {
        int w0 = (tid >> 2) * 4, hi = tid & 3;
        float a = 0.0f;
        #pragma unroll
        for (int w = 0; w < 4; w++) a += sl[w0 + w][hi];
        g_pl[bp * 8 + tid] = a;
    }
}

// ---------------------------------------------------------------------------
// K2: per batch — combine -> sbar -> ctx -> dec -> qf -> (w, kb). Coalesced.
// ---------------------------------------------------------------------------
__global__ void __launch_bounds__(128) k_epilogue(
    const float* __restrict__ Vb,  const float* __restrict__ Wob,
    const float* __restrict__ Qfb,
    const float* __restrict__ Kfw, const float* __restrict__ Kfb)
{
    const int b = blockIdx.x, tid = threadIdx.x;
    __shared__ float sbar[8 * 132];
    __shared__ float ctx[128], dec[128], qf[128], r2[128];
    __shared__ float invl[8];

    if (tid < 8) {
        float L = 0.0f;
        #pragma unroll
        for (int p = 0; p < SPLIT; p++)
            L += g_pl[(b * SPLIT + p) * 8 + tid];
        invl[tid] = 1.0f / L;
    }
    __syncthreads();

    #pragma unroll
    for (int hh = 0; hh < 8; hh++) {
        float a = 0.0f;
        #pragma unroll
        for (int p = 0; p < SPLIT; p++)
            a += g_ps[(size_t)(b * SPLIT + p) * 8 * E_ + hh * E_ + tid];
        sbar[hh * 132 + tid] = a * invl[hh];
    }
    __syncthreads();

    {
        const int hb_ = (tid >> 4) * 132;
        float a0 = Vb[tid], a1 = 0.f, a2 = 0.f, a3 = 0.f;
        #pragma unroll 8
        for (int k = 0; k < 128; k += 4) {
            a0 += g_VwT[(k + 0) * 128 + tid] * sbar[hb_ + k + 0];
            a1 += g_VwT[(k + 1) * 128 + tid] * sbar[hb_ + k + 1];
            a2 += g_VwT[(k + 2) * 128 + tid] * sbar[hb_ + k + 2];
            a3 += g_VwT[(k + 3) * 128 + tid] * sbar[hb_ + k + 3];
        }
        ctx[tid] = (a0 + a1) + (a2 + a3);
    }
    __syncthreads();
    {
        float a0 = Wob[tid], a1 = 0.f, a2 = 0.f, a3 = 0.f;
        #pragma unroll 8
        for (int k = 0; k < 128; k += 4) {
            a0 += g_WowT[(k + 0) * 128 + tid] * ctx[k + 0];
            a1 += g_WowT[(k + 1) * 128 + tid] * ctx[k + 1];
            a2 += g_WowT[(k + 2) * 128 + tid] * ctx[k + 2];
            a3 += g_WowT[(k + 3) * 128 + tid] * ctx[k + 3];
        }
        dec[tid] = (a0 + a1) + (a2 + a3);
    }
    __syncthreads();
    {
        float a0 = Qfb[tid], a1 = 0.f, a2 = 0.f, a3 = 0.f;
        #pragma unroll 8
        for (int k = 0; k < 128; k += 4) {
            a0 += g_QfwT[(k + 0) * 128 + tid] * dec[k + 0];
            a1 += g_QfwT[(k + 1) * 128 + tid] * dec[k + 1];
            a2 += g_QfwT[(k + 2) * 128 + tid] * dec[k + 2];
            a3 += g_QfwT[(k + 3) * 128 + tid] * dec[k + 3];
        }
        qf[tid] = (a0 + a1) + (a2 + a3);
    }
    __syncthreads();

    {
        float a0 = 0.f, a1 = 0.f, a2 = 0.f, a3 = 0.f;
        #pragma unroll 8
        for (int j = 0; j < 128; j += 4) {
            a0 += qf[j + 0] * Kfw[(size_t)(j + 0) * E_ + tid];
            a1 += qf[j + 1] * Kfw[(size_t)(j + 1) * E_ + tid];
            a2 += qf[j + 2] * Kfw[(size_t)(j + 2) * E_ + tid];
            a3 += qf[j + 3] * Kfw[(size_t)(j + 3) * E_ + tid];
        }
        g_w[b * 128 + tid] = (a0 + a1) + (a2 + a3);
    }
    r2[tid] = qf[tid] * Kfb[tid];
    __syncthreads();
    for (int st = 64; st; st >>= 1) {
        if (tid < st) r2[tid] += r2[tid + st];
        __syncthreads();
    }
    if (tid == 0) g_kb[b] = r2[0];
}

// ---------------------------------------------------------------------------
// K3: logits. Masked rows: write -1e8, never touch h. Unmasked: paired fold.
// ---------------------------------------------------------------------------
__global__ void __launch_bounds__(256) k_logits(
    const float* __restrict__ h, const int* __restrict__ mask,
    float* __restrict__ out)
{
    const int b = blockIdx.y, chunk = blockIdx.x;
    const int warp = threadIdx.x >> 5, lane = threadIdx.x & 31;

    float4 w4 = *(const float4*)&g_w[b * 128 + lane * 4];
    float  kb = g_kb[b];

    const int c0 = chunk * 256 + warp * 32;
    const float* rbase = h + ((size_t)b * C_ + c0) * E_ + lane * 4;
    float* ob = out + (size_t)b * C_ + c0;

    const int m = mask[b * C_ + c0 + lane];
    unsigned bits = __ballot_sync(0xffffffffu, m == 0);
    if (m) ob[lane] = -1.0e8f;

    const bool hi = (lane & 16) != 0;

    int i0 = -1, i1 = -1;
    if (bits) { i0 = __ffs(bits) - 1; bits &= bits - 1; }
    if (bits) { i1 = __ffs(bits) - 1; bits &= bits - 1; }
    float4 A0 = make_float4(0.f, 0.f, 0.f, 0.f), A1 = A0;
    if (i0 >= 0) {
        A0 = *(const float4*)(rbase + (size_t)i0 * E_);
        A1 = *(const float4*)(rbase + (size_t)(i1 >= 0 ? i1 : i0) * E_);
    }

    while (i0 >= 0) {
        int n0 = -1, n1 = -1;
        if (bits) { n0 = __ffs(bits) - 1; bits &= bits - 1; }
        if (bits) { n1 = __ffs(bits) - 1; bits &= bits - 1; }
        float4 N0, N1;
        if (n0 >= 0) {
            N0 = *(const float4*)(rbase + (size_t)n0 * E_);
            N1 = *(const float4*)(rbase + (size_t)(n1 >= 0 ? n1 : n0) * E_);
        }

        float p0 = A0.x * w4.x + A0.y * w4.y + A0.z * w4.z + A0.w * w4.w;
        float p1 = A1.x * w4.x + A1.y * w4.y + A1.z * w4.z + A1.w * w4.w;

        float send = hi ? p0 : p1;
        float keep = hi ? p1 : p0;
        float t = keep + __shfl_xor_sync(0xffffffffu, send, 16);
        t += __shfl_xor_sync(0xffffffffu, t, 8);
        t += __shfl_xor_sync(0xffffffffu, t, 4);
        t += __shfl_xor_sync(0xffffffffu, t, 2);
        t += __shfl_xor_sync(0xffffffffu, t, 1);

        float lg = (t + kb) * 0.08838834764831845f;
        float val = 10.0f * tanhf(lg);
        if (lane == 0)                  ob[i0] = val;
        else if (lane == 16 && i1 >= 0) ob[i1] = val;

        i0 = n0; i1 = n1; A0 = N0; A1 = N1;
    }
}

// ---------------------------------------------------------------------------
extern "C" void kernel_launch(void* const* d_in, const int* in_sizes, int n_in,
                              void* d_out, int out_size) {
    const float* h    = (const float*)d_in[0];
    const float* hN   = (const float*)d_in[1];
    const float* hpr  = (const float*)d_in[2];
    const float* h0   = (const float*)d_in[3];
    const int*   mask = (const int*)  d_in[4];
    const float* Qw   = (const float*)d_in[5];
    const float* Qb   = (const float*)d_in[6];
    const float* Vw   = (const float*)d_in[7];
    const float* Vb   = (const float*)d_in[8];
    const float* Wow  = (const float*)d_in[9];
    const float* Wob  = (const float*)d_in[10];
    const float* Qfw  = (const float*)d_in[11];
    const float* Qfb  = (const float*)d_in[12];
    const float* Kfw  = (const float*)d_in[13];
    const float* Kfb  = (const float*)d_in[14];
    float* out = (float*)d_out;

    const int DSMEM = 2 * TROWS * E_ * (int)sizeof(float);   // 64 KB
    cudaFuncSetAttribute(k_fused, cudaFuncAttributeMaxDynamicSharedMemorySize, DSMEM);

    k_setup   <<<dim3(SPLIT, B_), 256>>>(mask, Vw, Wow, Qfw, Qw);
    k_prep    <<<B_, 128>>>(hN, hpr, h0, Qb, Vw, Vb);
    k_fused   <<<dim3(SPLIT, B_), 256, DSMEM>>>(h);
    k_epilogue<<<B_, 128>>>(Vb, Wob, Qfb, Kfw, Kfb);
    k_logits  <<<dim3(4, B_), 256>>>(h, mask, out);
}